// round 12
// baseline (speedup 1.0000x reference)
#include <cuda_runtime.h>
#include <cstdint>
#include <math.h>

#define BB 128
#define TT 384
#define CC 256
#define NH 4
#define NKV 2
#define HD 64
#define M_ROWS (BB * TT)   // 49152

// ---------------- scratch (device globals; allocation is forbidden) --------
__device__ float g_qkv[(size_t)M_ROWS * 512];  // [B,T, q(256)|k(128)|v(128)]
__device__ float g_y[(size_t)M_ROWS * CC];     // attention output [B,T,C]
__device__ float2 g_rt[TT * 32];               // rope (cos,sin) table

// ---------------- helpers ---------------------------------------------------
__device__ __forceinline__ uint32_t smem_u32(const void* p) {
    uint32_t a;
    asm("{ .reg .u64 t; cvta.to.shared.u64 t, %1; cvt.u32.u64 %0, t; }"
        : "=r"(a) : "l"(p));
    return a;
}
__device__ __forceinline__ void cp16(uint32_t s, const void* g) {
    asm volatile("cp.async.cg.shared.global [%0], [%1], 16;" :: "r"(s), "l"(g));
}
__device__ __forceinline__ uint32_t f2tf32(float f) {
    uint32_t u;
    asm("cvt.rna.tf32.f32 %0, %1;" : "=r"(u) : "f"(f));
    return u;
}
__device__ __forceinline__ void mma_tf32(float* d, const uint32_t* a, const uint32_t* b) {
    asm volatile(
        "mma.sync.aligned.m16n8k8.row.col.f32.tf32.tf32.f32 "
        "{%0,%1,%2,%3}, {%4,%5,%6,%7}, {%8,%9}, {%0,%1,%2,%3};"
        : "+f"(d[0]), "+f"(d[1]), "+f"(d[2]), "+f"(d[3])
        : "r"(a[0]), "r"(a[1]), "r"(a[2]), "r"(a[3]), "r"(b[0]), "r"(b[1]));
}

// ---------------------------------------------------------------------------
// Shared tf32 GEMM tile body (128x128 tile, K=256).
// ---------------------------------------------------------------------------
#define GK 256
#define GBK 32
#define A_STRIDE 36
#define B_STRIDE 136
#define A_FLOATS (128 * A_STRIDE)
#define STAGE_FLOATS (A_FLOATS + GBK * B_STRIDE)
#define GSMEM_BYTES (2 * STAGE_FLOATS * 4)

__device__ __forceinline__ void gemm_tile_128(const float* __restrict__ A,
                                              const float* __restrict__ W,
                                              float* __restrict__ Ct,
                                              int ldW, int ldC) {
    extern __shared__ float smem[];
    const uint32_t sbase = smem_u32(smem);

    const int tid  = threadIdx.x;
    const int warp = tid >> 5;
    const int lane = tid & 31;
    const int gid  = lane >> 2;
    const int tig  = lane & 3;
    const int warpM = (warp & 1) * 64;
    const int warpN = (warp >> 1) * 32;

    float acc[4][4][4];
#pragma unroll
    for (int mt = 0; mt < 4; mt++)
#pragma unroll
        for (int nt = 0; nt < 4; nt++)
#pragma unroll
            for (int r = 0; r < 4; r++) acc[mt][nt][r] = 0.f;

    auto load_stage = [&](int stage, int k0) {
        uint32_t sa = sbase + stage * (STAGE_FLOATS * 4);
        uint32_t sb = sa + A_FLOATS * 4;
        const float* Ag = A + k0;
        const float* Wg = W + (size_t)k0 * ldW;
#pragma unroll
        for (int i = 0; i < 4; i++) {
            int id = tid + i * 256;
            int m = id >> 3, c4 = id & 7;
            cp16(sa + (m * A_STRIDE + c4 * 4) * 4, Ag + (size_t)m * GK + c4 * 4);
        }
#pragma unroll
        for (int i = 0; i < 4; i++) {
            int id = tid + i * 256;
            int kk = id >> 5, c4 = id & 31;
            cp16(sb + (kk * B_STRIDE + c4 * 4) * 4, Wg + (size_t)kk * ldW + c4 * 4);
        }
        asm volatile("cp.async.commit_group;" ::: "memory");
    };

    auto compute_stage = [&](int stage) {
        const float* sa = smem + stage * STAGE_FLOATS;
        const float* sb = sa + A_FLOATS;
#pragma unroll
        for (int ks = 0; ks < 4; ks++) {
            const int kc = ks * 8;
            uint32_t bf[4][2];
#pragma unroll
            for (int nt = 0; nt < 4; nt++) {
                int col = warpN + nt * 8 + gid;
                bf[nt][0] = f2tf32(sb[(kc + tig) * B_STRIDE + col]);
                bf[nt][1] = f2tf32(sb[(kc + tig + 4) * B_STRIDE + col]);
            }
#pragma unroll
            for (int mt = 0; mt < 4; mt++) {
                int row = warpM + mt * 16 + gid;
                uint32_t af[4];
                af[0] = f2tf32(sa[row * A_STRIDE + kc + tig]);
                af[1] = f2tf32(sa[(row + 8) * A_STRIDE + kc + tig]);
                af[2] = f2tf32(sa[row * A_STRIDE + kc + tig + 4]);
                af[3] = f2tf32(sa[(row + 8) * A_STRIDE + kc + tig + 4]);
#pragma unroll
                for (int nt = 0; nt < 4; nt++) mma_tf32(acc[mt][nt], af, bf[nt]);
            }
        }
    };

    load_stage(0, 0);
#pragma unroll
    for (int it = 0; it < 8; it++) {
        if (it + 1 < 8) {
            load_stage((it + 1) & 1, (it + 1) * GBK);
            asm volatile("cp.async.wait_group 1;" ::: "memory");
        } else {
            asm volatile("cp.async.wait_group 0;" ::: "memory");
        }
        __syncthreads();
        compute_stage(it & 1);
        __syncthreads();
    }

#pragma unroll
    for (int mt = 0; mt < 4; mt++) {
        int row = warpM + mt * 16 + gid;
#pragma unroll
        for (int nt = 0; nt < 4; nt++) {
            int col = warpN + nt * 8 + tig * 2;
            *(float2*)(Ct + (size_t)row * ldC + col) =
                make_float2(acc[mt][nt][0], acc[mt][nt][1]);
            *(float2*)(Ct + (size_t)(row + 8) * ldC + col) =
                make_float2(acc[mt][nt][2], acc[mt][nt][3]);
        }
    }
}

__global__ void __launch_bounds__(256, 2)
gemm_qkv_kernel(const float* __restrict__ x, const float* __restrict__ Wq,
                const float* __restrict__ Wk, const float* __restrict__ Wv,
                float* __restrict__ qkv) {
    const int bx = blockIdx.x, by = blockIdx.y;
    const float* W;
    int ldW;
    if (bx < 2)      { W = Wq + bx * 128; ldW = 256; }
    else if (bx == 2){ W = Wk;            ldW = 128; }
    else             { W = Wv;            ldW = 128; }
    gemm_tile_128(x + (size_t)by * 128 * GK, W,
                  qkv + (size_t)by * 128 * 512 + bx * 128, ldW, 512);
}

__global__ void __launch_bounds__(256, 2)
gemm_out_kernel(const float* __restrict__ y, const float* __restrict__ Wo,
                float* __restrict__ out) {
    const int bx = blockIdx.x, by = blockIdx.y;
    gemm_tile_128(y + (size_t)by * 128 * GK, Wo + bx * 128,
                  out + (size_t)by * 128 * 256 + bx * 128, 256, 256);
}

// ---------------------------------------------------------------------------
// RoPE table: g_rt[t*32+p] = (cos, sin) of t * 10000^(-p/32).
// ---------------------------------------------------------------------------
__global__ void rope_table_kernel() {
    int idx = blockIdx.x * blockDim.x + threadIdx.x;
    if (idx >= TT * 32) return;
    int t = idx >> 5, p = idx & 31;
    const float kLog2_10000_over32 = 0.41524101186407246f;
    float inv = exp2f(-(float)p * kLog2_10000_over32);
    float c, s;
    sincosf((float)t * inv, &s, &c);
    g_rt[idx] = make_float2(c, s);
}

// ---------------------------------------------------------------------------
// Tensor-core flash attention with fused rope + register-prefetch pipeline.
// Grid (T/64, H, B), 128 threads. Kt[d][key] stride 72, Vs[key][d] stride 72.
// ---------------------------------------------------------------------------
#define KSTR 72

__global__ void __launch_bounds__(128)
attn_mma_kernel(const float* __restrict__ qkv, const float2* __restrict__ rt,
                float* __restrict__ y) {
    __shared__ uint32_t Kt[64 * KSTR];
    __shared__ uint32_t Vs[64 * KSTR];

    const int qb = blockIdx.x;
    const int h  = blockIdx.y;
    const int b  = blockIdx.z;
    const int g  = h >> 1;
    const int tid = threadIdx.x;
    const int w = tid >> 5;
    const int lane = tid & 31;
    const int gid = lane >> 2;
    const int tig = lane & 3;

    const float* qp = qkv + (size_t)(b * TT) * 512 + h * 64;
    const float* kp = qkv + (size_t)(b * TT) * 512 + 256 + g * 64;
    const float* vp = kp + 128;

    // ---- stage Q tile: rope + scale into exp2 domain, via Vs ----
    const float qscale = 0.18033688011112042f;  // 0.125 * log2(e)
#pragma unroll
    for (int it = 0; it < 4; it++) {
        int i = tid + it * 128;          // 0..511
        int r = i >> 3, c4 = i & 7;      // row 0..63, lower-half float4 idx
        int t = qb * 64 + r;
        const float* src = qp + (size_t)t * 512 + c4 * 4;
        float4 lo = *(const float4*)(src);
        float4 hi = *(const float4*)(src + 32);
        float2 cs0 = rt[t * 32 + c4 * 4 + 0];
        float2 cs1 = rt[t * 32 + c4 * 4 + 1];
        float2 cs2 = rt[t * 32 + c4 * 4 + 2];
        float2 cs3 = rt[t * 32 + c4 * 4 + 3];
        uint32_t* dlo = &Vs[r * KSTR + c4 * 4];
        dlo[0] = __float_as_uint((lo.x * cs0.x - hi.x * cs0.y) * qscale);
        dlo[1] = __float_as_uint((lo.y * cs1.x - hi.y * cs1.y) * qscale);
        dlo[2] = __float_as_uint((lo.z * cs2.x - hi.z * cs2.y) * qscale);
        dlo[3] = __float_as_uint((lo.w * cs3.x - hi.w * cs3.y) * qscale);
        dlo[32] = __float_as_uint((hi.x * cs0.x + lo.x * cs0.y) * qscale);
        dlo[33] = __float_as_uint((hi.y * cs1.x + lo.y * cs1.y) * qscale);
        dlo[34] = __float_as_uint((hi.z * cs2.x + lo.z * cs2.y) * qscale);
        dlo[35] = __float_as_uint((hi.w * cs3.x + lo.w * cs3.y) * qscale);
    }
    __syncthreads();
    uint32_t aq[8][4];
    {
        int r0 = w * 16 + gid;
#pragma unroll
        for (int o = 0; o < 8; o++) {
            aq[o][0] = f2tf32(__uint_as_float(Vs[r0 * KSTR + o * 8 + tig]));
            aq[o][1] = f2tf32(__uint_as_float(Vs[(r0 + 8) * KSTR + o * 8 + tig]));
            aq[o][2] = f2tf32(__uint_as_float(Vs[r0 * KSTR + o * 8 + tig + 4]));
            aq[o][3] = f2tf32(__uint_as_float(Vs[(r0 + 8) * KSTR + o * 8 + tig + 4]));
        }
    }

    float m0 = -1e30f, m1 = -1e30f, l0 = 0.f, l1 = 0.f;
    float oacc[8][4];
#pragma unroll
    for (int nf = 0; nf < 8; nf++)
#pragma unroll
        for (int c = 0; c < 4; c++) oacc[nf][c] = 0.f;

    // ---- register-prefetch staging pipeline ----
    float4 pV[8], pKlo[4], pKhi[4];

    auto ldg_tile = [&](int kb) {
#pragma unroll
        for (int it = 0; it < 8; it++) {
            int i = tid + it * 128;
            int key = i >> 4, c4 = i & 15;
            pV[it] = *(const float4*)(vp + (size_t)(kb + key) * 512 + c4 * 4);
        }
#pragma unroll
        for (int it = 0; it < 4; it++) {
            int i = tid + it * 128;      // 0..511
            int key = i & 63, c4h = i >> 6;   // c4h 0..7 covers d 0..31
            const float* src = kp + (size_t)(kb + key) * 512 + c4h * 4;
            pKlo[it] = *(const float4*)(src);
            pKhi[it] = *(const float4*)(src + 32);
        }
    };

    auto sts_tile = [&](int kb) {
        // K: rope + transpose store (conflict-free: bank = lane)
#pragma unroll
        for (int it = 0; it < 4; it++) {
            int i = tid + it * 128;
            int key = i & 63, c4h = i >> 6;
            int t = kb + key;
            float4 lo = pKlo[it], hi = pKhi[it];
            float2 cs0 = rt[t * 32 + c4h * 4 + 0];
            float2 cs1 = rt[t * 32 + c4h * 4 + 1];
            float2 cs2 = rt[t * 32 + c4h * 4 + 2];
            float2 cs3 = rt[t * 32 + c4h * 4 + 3];
            int d = c4h * 4;
            Kt[(d + 0) * KSTR + key] = f2tf32(lo.x * cs0.x - hi.x * cs0.y);
            Kt[(d + 1) * KSTR + key] = f2tf32(lo.y * cs1.x - hi.y * cs1.y);
            Kt[(d + 2) * KSTR + key] = f2tf32(lo.z * cs2.x - hi.z * cs2.y);
            Kt[(d + 3) * KSTR + key] = f2tf32(lo.w * cs3.x - hi.w * cs3.y);
            Kt[(d + 32) * KSTR + key] = f2tf32(hi.x * cs0.x + lo.x * cs0.y);
            Kt[(d + 33) * KSTR + key] = f2tf32(hi.y * cs1.x + lo.y * cs1.y);
            Kt[(d + 34) * KSTR + key] = f2tf32(hi.z * cs2.x + lo.z * cs2.y);
            Kt[(d + 35) * KSTR + key] = f2tf32(hi.w * cs3.x + lo.w * cs3.y);
        }
        // V: tf32 convert, float4 store
#pragma unroll
        for (int it = 0; it < 8; it++) {
            int i = tid + it * 128;
            int key = i >> 4, c4 = i & 15;
            uint4 u;
            u.x = f2tf32(pV[it].x); u.y = f2tf32(pV[it].y);
            u.z = f2tf32(pV[it].z); u.w = f2tf32(pV[it].w);
            *(uint4*)&Vs[key * KSTR + c4 * 4] = u;
        }
    };

    ldg_tile(0);

    for (int kt = 0; kt <= qb; kt++) {
        __syncthreads();               // all warps done reading smem
        sts_tile(kt * 64);
        __syncthreads();
        if (kt < qb) ldg_tile((kt + 1) * 64);   // overlap LDG with compute

        // ---- S = Q @ K^T ----
        float sacc[8][4];
#pragma unroll
        for (int nf = 0; nf < 8; nf++)
#pragma unroll
            for (int c = 0; c < 4; c++) sacc[nf][c] = 0.f;
#pragma unroll
        for (int nf = 0; nf < 8; nf++) {
#pragma unroll
            for (int o = 0; o < 8; o++) {
                uint32_t bk[2];
                bk[0] = Kt[(o * 8 + tig) * KSTR + nf * 8 + gid];
                bk[1] = Kt[(o * 8 + tig + 4) * KSTR + nf * 8 + gid];
                mma_tf32(sacc[nf], aq[o], bk);
            }
        }

        // ---- causal mask on diagonal tile ----
        if (kt == qb) {
            int jr0 = w * 16 + gid, jr1 = jr0 + 8;
#pragma unroll
            for (int nf = 0; nf < 8; nf++) {
                int jc = nf * 8 + 2 * tig;
                if (jc > jr0)     sacc[nf][0] = -1e30f;
                if (jc + 1 > jr0) sacc[nf][1] = -1e30f;
                if (jc > jr1)     sacc[nf][2] = -1e30f;
                if (jc + 1 > jr1) sacc[nf][3] = -1e30f;
            }
        }

        // ---- online softmax (exp2 domain) ----
        float rx0 = -1e30f, rx1 = -1e30f;
#pragma unroll
        for (int nf = 0; nf < 8; nf++) {
            rx0 = fmaxf(rx0, fmaxf(sacc[nf][0], sacc[nf][1]));
            rx1 = fmaxf(rx1, fmaxf(sacc[nf][2], sacc[nf][3]));
        }
        rx0 = fmaxf(rx0, __shfl_xor_sync(0xffffffffu, rx0, 1));
        rx0 = fmaxf(rx0, __shfl_xor_sync(0xffffffffu, rx0, 2));
        rx1 = fmaxf(rx1, __shfl_xor_sync(0xffffffffu, rx1, 1));
        rx1 = fmaxf(rx1, __shfl_xor_sync(0xffffffffu, rx1, 2));
        float mn0 = fmaxf(m0, rx0), mn1 = fmaxf(m1, rx1);
        float corr0 = exp2f(m0 - mn0), corr1 = exp2f(m1 - mn1);
        m0 = mn0; m1 = mn1;
        float rs0 = 0.f, rs1 = 0.f;
#pragma unroll
        for (int nf = 0; nf < 8; nf++) {
            sacc[nf][0] = exp2f(sacc[nf][0] - m0);
            sacc[nf][1] = exp2f(sacc[nf][1] - m0);
            sacc[nf][2] = exp2f(sacc[nf][2] - m1);
            sacc[nf][3] = exp2f(sacc[nf][3] - m1);
            rs0 += sacc[nf][0] + sacc[nf][1];
            rs1 += sacc[nf][2] + sacc[nf][3];
        }
        rs0 += __shfl_xor_sync(0xffffffffu, rs0, 1);
        rs0 += __shfl_xor_sync(0xffffffffu, rs0, 2);
        rs1 += __shfl_xor_sync(0xffffffffu, rs1, 1);
        rs1 += __shfl_xor_sync(0xffffffffu, rs1, 2);
        l0 = l0 * corr0 + rs0;
        l1 = l1 * corr1 + rs1;
#pragma unroll
        for (int nf = 0; nf < 8; nf++) {
            oacc[nf][0] *= corr0; oacc[nf][1] *= corr0;
            oacc[nf][2] *= corr1; oacc[nf][3] *= corr1;
        }

        // ---- O += P @ V (C-layout -> A-layout via shuffles) ----
        const int srcA = (gid << 2) + (tig >> 1);
        const int srcB = srcA + 2;
        const bool odd = tig & 1;
#pragma unroll
        for (int ko = 0; ko < 8; ko++) {
            float s0a = __shfl_sync(0xffffffffu, sacc[ko][0], srcA);
            float s1a = __shfl_sync(0xffffffffu, sacc[ko][1], srcA);
            float s2a = __shfl_sync(0xffffffffu, sacc[ko][2], srcA);
            float s3a = __shfl_sync(0xffffffffu, sacc[ko][3], srcA);
            float s0b = __shfl_sync(0xffffffffu, sacc[ko][0], srcB);
            float s1b = __shfl_sync(0xffffffffu, sacc[ko][1], srcB);
            float s2b = __shfl_sync(0xffffffffu, sacc[ko][2], srcB);
            float s3b = __shfl_sync(0xffffffffu, sacc[ko][3], srcB);
            uint32_t pa[4];
            pa[0] = f2tf32(odd ? s1a : s0a);
            pa[1] = f2tf32(odd ? s3a : s2a);
            pa[2] = f2tf32(odd ? s1b : s0b);
            pa[3] = f2tf32(odd ? s3b : s2b);
#pragma unroll
            for (int nd = 0; nd < 8; nd++) {
                uint32_t bv[2];
                bv[0] = Vs[(ko * 8 + tig) * KSTR + nd * 8 + gid];
                bv[1] = Vs[(ko * 8 + tig + 4) * KSTR + nd * 8 + gid];
                mma_tf32(oacc[nd], pa, bv);
            }
        }
    }

    // ---- epilogue ----
    float il0 = 1.f / l0, il1 = 1.f / l1;
    float* y0 = y + (size_t)(b * TT + qb * 64 + w * 16 + gid) * 256 + h * 64;
    float* y1 = y0 + (size_t)8 * 256;
#pragma unroll
    for (int nf = 0; nf < 8; nf++) {
        *(float2*)(y0 + nf * 8 + 2 * tig) =
            make_float2(oacc[nf][0] * il0, oacc[nf][1] * il0);
        *(float2*)(y1 + nf * 8 + 2 * tig) =
            make_float2(oacc[nf][2] * il1, oacc[nf][3] * il1);
    }
}

// ---------------------------------------------------------------------------
extern "C" void kernel_launch(void* const* d_in, const int* in_sizes, int n_in,
                              void* d_out, int out_size) {
    const float* x  = (const float*)d_in[0];
    const float* Wq = (const float*)d_in[1];
    const float* Wk = (const float*)d_in[2];
    const float* Wv = (const float*)d_in[3];
    const float* Wo = (const float*)d_in[4];
    float* out = (float*)d_out;

    float *qkv, *y;
    float2* rt;
    cudaGetSymbolAddress((void**)&qkv, g_qkv);
    cudaGetSymbolAddress((void**)&y, g_y);
    cudaGetSymbolAddress((void**)&rt, g_rt);

    cudaFuncSetAttribute(gemm_qkv_kernel,
                         cudaFuncAttributeMaxDynamicSharedMemorySize, GSMEM_BYTES);
    cudaFuncSetAttribute(gemm_out_kernel,
                         cudaFuncAttributeMaxDynamicSharedMemorySize, GSMEM_BYTES);

    // rope table (tiny; overlaps nothing it depends on)
    rope_table_kernel<<<(TT * 32 + 255) / 256, 256>>>();

    // fused QKV projection -> qkv[M][512]
    gemm_qkv_kernel<<<dim3(4, M_ROWS / 128), 256, GSMEM_BYTES>>>(x, Wq, Wk, Wv, qkv);

    // tensor-core flash attention with fused rope -> y[M][256]
    {
        dim3 ga(TT / 64, NH, BB);
        attn_mma_kernel<<<ga, 128>>>(qkv, rt, y);
    }

    // output projection
    gemm_out_kernel<<<dim3(2, M_ROWS / 128), 256, GSMEM_BYTES>>>(y, Wo, out);
}

// round 13
// speedup vs baseline: 1.1437x; 1.1437x over previous
#include <cuda_runtime.h>
#include <cuda_fp16.h>
#include <cstdint>
#include <math.h>

#define BB 128
#define TT 384
#define CC 256
#define NH 4
#define NKV 2
#define HD 64
#define M_ROWS (BB * TT)   // 49152

// ---------------- scratch (device globals; allocation is forbidden) --------
__device__ __half g_xh[(size_t)M_ROWS * 256];   // x in half
__device__ float  g_qkv[(size_t)M_ROWS * 512];  // [B,T, q(256)|k(128)|v(128)]
__device__ __half g_yh[(size_t)M_ROWS * CC];    // attention output, half
__device__ __half g_wqt[256 * 256];             // W^T in half: [n][k]
__device__ __half g_wkt[128 * 256];
__device__ __half g_wvt[128 * 256];
__device__ __half g_wot[256 * 256];
__device__ float2 g_rt[TT * 32];                // rope (cos,sin) table

// ---------------- helpers ---------------------------------------------------
__device__ __forceinline__ uint32_t smem_u32(const void* p) {
    uint32_t a;
    asm("{ .reg .u64 t; cvta.to.shared.u64 t, %1; cvt.u32.u64 %0, t; }"
        : "=r"(a) : "l"(p));
    return a;
}
__device__ __forceinline__ void cp16(uint32_t s, const void* g) {
    asm volatile("cp.async.cg.shared.global [%0], [%1], 16;" :: "r"(s), "l"(g));
}
__device__ __forceinline__ uint32_t f2tf32(float f) {
    uint32_t u;
    asm("cvt.rna.tf32.f32 %0, %1;" : "=r"(u) : "f"(f));
    return u;
}
__device__ __forceinline__ void mma_tf32(float* d, const uint32_t* a, const uint32_t* b) {
    asm volatile(
        "mma.sync.aligned.m16n8k8.row.col.f32.tf32.tf32.f32 "
        "{%0,%1,%2,%3}, {%4,%5,%6,%7}, {%8,%9}, {%0,%1,%2,%3};"
        : "+f"(d[0]), "+f"(d[1]), "+f"(d[2]), "+f"(d[3])
        : "r"(a[0]), "r"(a[1]), "r"(a[2]), "r"(a[3]), "r"(b[0]), "r"(b[1]));
}
__device__ __forceinline__ void mma_f16(float* d, const uint32_t* a, const uint32_t* b) {
    asm volatile(
        "mma.sync.aligned.m16n8k16.row.col.f32.f16.f16.f32 "
        "{%0,%1,%2,%3}, {%4,%5,%6,%7}, {%8,%9}, {%0,%1,%2,%3};"
        : "+f"(d[0]), "+f"(d[1]), "+f"(d[2]), "+f"(d[3])
        : "r"(a[0]), "r"(a[1]), "r"(a[2]), "r"(a[3]), "r"(b[0]), "r"(b[1]));
}

// ---------------------------------------------------------------------------
// Pre-convert kernels
// ---------------------------------------------------------------------------
__global__ void cvt_x_kernel(const float* __restrict__ x) {
    size_t j = (size_t)blockIdx.x * blockDim.x + threadIdx.x;   // 8 elems each
    if (j >= (size_t)M_ROWS * 32) return;
    const float4* xs = (const float4*)x;
    float4 f0 = xs[j * 2], f1 = xs[j * 2 + 1];
    __half2 h0 = __floats2half2_rn(f0.x, f0.y);
    __half2 h1 = __floats2half2_rn(f0.z, f0.w);
    __half2 h2 = __floats2half2_rn(f1.x, f1.y);
    __half2 h3 = __floats2half2_rn(f1.z, f1.w);
    uint4 u;
    u.x = *(uint32_t*)&h0; u.y = *(uint32_t*)&h1;
    u.z = *(uint32_t*)&h2; u.w = *(uint32_t*)&h3;
    ((uint4*)g_xh)[j] = u;
}

// transpose + convert all weights: W[k][n] float -> Wt[n][k] half
__global__ void cvt_w_kernel(const float* __restrict__ Wq, const float* __restrict__ Wk,
                             const float* __restrict__ Wv, const float* __restrict__ Wo) {
    int i = blockIdx.x * blockDim.x + threadIdx.x;
    if (i < 65536) {
        int n = i >> 8, k = i & 255;
        g_wqt[i] = __float2half(Wq[k * 256 + n]);
    } else if (i < 98304) {
        int i2 = i - 65536;
        int n = i2 >> 8, k = i2 & 255;
        g_wkt[i2] = __float2half(Wk[k * 128 + n]);
    } else if (i < 131072) {
        int i2 = i - 98304;
        int n = i2 >> 8, k = i2 & 255;
        g_wvt[i2] = __float2half(Wv[k * 128 + n]);
    } else if (i < 196608) {
        int i2 = i - 131072;
        int n = i2 >> 8, k = i2 & 255;
        g_wot[i2] = __float2half(Wo[k * 256 + n]);
    }
}

// ---------------------------------------------------------------------------
// fp16 m16n8k16 GEMM tile: C[128,128(tile)] = Ah[128rows,K=256] @ Bt[n][k]^T.
// Both operands staged identically: 128 rows x 32 halves, stride 40 halves
// (pad 8 -> bank (20*gid+tig) mod 32 bijective; 80B rows, 16B-aligned chunks).
// 256 threads, 8 warps of 64x32, 2-stage cp.async, BK=32 (2 k16 steps).
// ---------------------------------------------------------------------------
#define HSTR 40
#define HOP_HALVES (128 * HSTR)            // 5120 halves per operand
#define HSTAGE_HALVES (2 * HOP_HALVES)     // 10240
#define HSMEM_BYTES (2 * HSTAGE_HALVES * 2)  // 40960

__device__ __forceinline__ void hgemm_tile_128(const __half* __restrict__ Ah,
                                               const __half* __restrict__ Bt,
                                               float* __restrict__ Ct, int ldC) {
    extern __shared__ __half hsm[];
    const uint32_t sbase = smem_u32(hsm);

    const int tid  = threadIdx.x;
    const int warp = tid >> 5;
    const int lane = tid & 31;
    const int gid  = lane >> 2;
    const int tig  = lane & 3;
    const int warpM = (warp & 1) * 64;
    const int warpN = (warp >> 1) * 32;

    float acc[4][4][4];
#pragma unroll
    for (int mt = 0; mt < 4; mt++)
#pragma unroll
        for (int nt = 0; nt < 4; nt++)
#pragma unroll
            for (int r = 0; r < 4; r++) acc[mt][nt][r] = 0.f;

    auto load_stage = [&](int stage, int k0) {
        uint32_t sa = sbase + stage * (HSTAGE_HALVES * 2);
        uint32_t sb = sa + HOP_HALVES * 2;
#pragma unroll
        for (int i = 0; i < 2; i++) {
            int id = tid + i * 256;          // 0..511
            int row = id >> 2, c4 = id & 3;  // 4 x 16B chunks per 64B row
            cp16(sa + row * 80 + c4 * 16, Ah + (size_t)row * 256 + k0 + c4 * 8);
            cp16(sb + row * 80 + c4 * 16, Bt + (size_t)row * 256 + k0 + c4 * 8);
        }
        asm volatile("cp.async.commit_group;" ::: "memory");
    };

    auto compute_stage = [&](int stage) {
        const __half* sa = hsm + stage * HSTAGE_HALVES;
        const __half* sb = sa + HOP_HALVES;
#pragma unroll
        for (int ks = 0; ks < 2; ks++) {
            const int kc = ks * 16;
            uint32_t bf[4][2];
#pragma unroll
            for (int nt = 0; nt < 4; nt++) {
                int n = warpN + nt * 8 + gid;
                bf[nt][0] = *(const uint32_t*)&sb[n * HSTR + kc + 2 * tig];
                bf[nt][1] = *(const uint32_t*)&sb[n * HSTR + kc + 8 + 2 * tig];
            }
#pragma unroll
            for (int mt = 0; mt < 4; mt++) {
                int r = warpM + mt * 16 + gid;
                uint32_t af[4];
                af[0] = *(const uint32_t*)&sa[r * HSTR + kc + 2 * tig];
                af[1] = *(const uint32_t*)&sa[(r + 8) * HSTR + kc + 2 * tig];
                af[2] = *(const uint32_t*)&sa[r * HSTR + kc + 8 + 2 * tig];
                af[3] = *(const uint32_t*)&sa[(r + 8) * HSTR + kc + 8 + 2 * tig];
#pragma unroll
                for (int nt = 0; nt < 4; nt++) mma_f16(acc[mt][nt], af, bf[nt]);
            }
        }
    };

    load_stage(0, 0);
#pragma unroll
    for (int it = 0; it < 8; it++) {
        if (it + 1 < 8) {
            load_stage((it + 1) & 1, (it + 1) * 32);
            asm volatile("cp.async.wait_group 1;" ::: "memory");
        } else {
            asm volatile("cp.async.wait_group 0;" ::: "memory");
        }
        __syncthreads();
        compute_stage(it & 1);
        __syncthreads();
    }

#pragma unroll
    for (int mt = 0; mt < 4; mt++) {
        int row = warpM + mt * 16 + gid;
#pragma unroll
        for (int nt = 0; nt < 4; nt++) {
            int col = warpN + nt * 8 + tig * 2;
            *(float2*)(Ct + (size_t)row * ldC + col) =
                make_float2(acc[mt][nt][0], acc[mt][nt][1]);
            *(float2*)(Ct + (size_t)(row + 8) * ldC + col) =
                make_float2(acc[mt][nt][2], acc[mt][nt][3]);
        }
    }
}

__global__ void __launch_bounds__(256, 2)
hgemm_qkv_kernel(float* __restrict__ qkv) {
    const int bx = blockIdx.x, by = blockIdx.y;
    const __half* Bt;
    if (bx < 2)       Bt = g_wqt + bx * 128 * 256;
    else if (bx == 2) Bt = g_wkt;
    else              Bt = g_wvt;
    hgemm_tile_128(g_xh + (size_t)by * 128 * 256, Bt,
                   qkv + (size_t)by * 128 * 512 + bx * 128, 512);
}

__global__ void __launch_bounds__(256, 2)
hgemm_out_kernel(float* __restrict__ out) {
    const int bx = blockIdx.x, by = blockIdx.y;
    hgemm_tile_128(g_yh + (size_t)by * 128 * 256, g_wot + bx * 128 * 256,
                   out + (size_t)by * 128 * 256 + bx * 128, 256);
}

// ---------------------------------------------------------------------------
// RoPE table: g_rt[t*32+p] = (cos, sin) of t * 10000^(-p/32).
// ---------------------------------------------------------------------------
__global__ void rope_table_kernel() {
    int idx = blockIdx.x * blockDim.x + threadIdx.x;
    if (idx >= TT * 32) return;
    int t = idx >> 5, p = idx & 31;
    const float kLog2_10000_over32 = 0.41524101186407246f;
    float inv = exp2f(-(float)p * kLog2_10000_over32);
    float c, s;
    sincosf((float)t * inv, &s, &c);
    g_rt[idx] = make_float2(c, s);
}

// ---------------------------------------------------------------------------
// Tensor-core flash attention (tf32), rope fused into SERIAL staging (no
// register prefetch -- that regressed in R12). Grid (T/64, H, B), 128 thr.
// Kt[d][key] stride 72 (conflict-free), Vs[key][d] stride 72. Output: half.
// ---------------------------------------------------------------------------
#define KSTR 72

__global__ void __launch_bounds__(128)
attn_mma_kernel(const float* __restrict__ qkv, const float2* __restrict__ rt,
                __half* __restrict__ y) {
    __shared__ uint32_t Kt[64 * KSTR];
    __shared__ uint32_t Vs[64 * KSTR];

    const int qb = blockIdx.x;
    const int h  = blockIdx.y;
    const int b  = blockIdx.z;
    const int g  = h >> 1;
    const int tid = threadIdx.x;
    const int w = tid >> 5;
    const int lane = tid & 31;
    const int gid = lane >> 2;
    const int tig = lane & 3;

    const float* qp = qkv + (size_t)(b * TT) * 512 + h * 64;
    const float* kp = qkv + (size_t)(b * TT) * 512 + 256 + g * 64;
    const float* vp = kp + 128;

    // ---- stage Q tile: rope + scale into exp2 domain, via Vs ----
    const float qscale = 0.18033688011112042f;  // 0.125 * log2(e)
#pragma unroll
    for (int it = 0; it < 4; it++) {
        int i = tid + it * 128;          // 0..511
        int r = i >> 3, c4 = i & 7;      // row 0..63, lower-half float4 idx
        int t = qb * 64 + r;
        const float* src = qp + (size_t)t * 512 + c4 * 4;
        float4 lo = *(const float4*)(src);
        float4 hi = *(const float4*)(src + 32);
        float2 cs0 = rt[t * 32 + c4 * 4 + 0];
        float2 cs1 = rt[t * 32 + c4 * 4 + 1];
        float2 cs2 = rt[t * 32 + c4 * 4 + 2];
        float2 cs3 = rt[t * 32 + c4 * 4 + 3];
        uint32_t* dlo = &Vs[r * KSTR + c4 * 4];
        dlo[0] = __float_as_uint((lo.x * cs0.x - hi.x * cs0.y) * qscale);
        dlo[1] = __float_as_uint((lo.y * cs1.x - hi.y * cs1.y) * qscale);
        dlo[2] = __float_as_uint((lo.z * cs2.x - hi.z * cs2.y) * qscale);
        dlo[3] = __float_as_uint((lo.w * cs3.x - hi.w * cs3.y) * qscale);
        dlo[32] = __float_as_uint((hi.x * cs0.x + lo.x * cs0.y) * qscale);
        dlo[33] = __float_as_uint((hi.y * cs1.x + lo.y * cs1.y) * qscale);
        dlo[34] = __float_as_uint((hi.z * cs2.x + lo.z * cs2.y) * qscale);
        dlo[35] = __float_as_uint((hi.w * cs3.x + lo.w * cs3.y) * qscale);
    }
    __syncthreads();
    uint32_t aq[8][4];
    {
        int r0 = w * 16 + gid;
#pragma unroll
        for (int o = 0; o < 8; o++) {
            aq[o][0] = f2tf32(__uint_as_float(Vs[r0 * KSTR + o * 8 + tig]));
            aq[o][1] = f2tf32(__uint_as_float(Vs[(r0 + 8) * KSTR + o * 8 + tig]));
            aq[o][2] = f2tf32(__uint_as_float(Vs[r0 * KSTR + o * 8 + tig + 4]));
            aq[o][3] = f2tf32(__uint_as_float(Vs[(r0 + 8) * KSTR + o * 8 + tig + 4]));
        }
    }

    float m0 = -1e30f, m1 = -1e30f, l0 = 0.f, l1 = 0.f;
    float oacc[8][4];
#pragma unroll
    for (int nf = 0; nf < 8; nf++)
#pragma unroll
        for (int c = 0; c < 4; c++) oacc[nf][c] = 0.f;

    for (int kt = 0; kt <= qb; kt++) {
        const int kb = kt * 64;
        __syncthreads();   // all warps done reading previous tile
        // K: rope + transpose store (serial LDG->rope->STS, transient regs)
#pragma unroll
        for (int it = 0; it < 4; it++) {
            int i = tid + it * 128;
            int key = i & 63, c4h = i >> 6;   // c4h 0..7
            int t = kb + key;
            const float* src = kp + (size_t)t * 512 + c4h * 4;
            float4 lo = *(const float4*)(src);
            float4 hi = *(const float4*)(src + 32);
            float2 cs0 = rt[t * 32 + c4h * 4 + 0];
            float2 cs1 = rt[t * 32 + c4h * 4 + 1];
            float2 cs2 = rt[t * 32 + c4h * 4 + 2];
            float2 cs3 = rt[t * 32 + c4h * 4 + 3];
            int d = c4h * 4;
            Kt[(d + 0) * KSTR + key] = f2tf32(lo.x * cs0.x - hi.x * cs0.y);
            Kt[(d + 1) * KSTR + key] = f2tf32(lo.y * cs1.x - hi.y * cs1.y);
            Kt[(d + 2) * KSTR + key] = f2tf32(lo.z * cs2.x - hi.z * cs2.y);
            Kt[(d + 3) * KSTR + key] = f2tf32(lo.w * cs3.x - hi.w * cs3.y);
            Kt[(d + 32) * KSTR + key] = f2tf32(hi.x * cs0.x + lo.x * cs0.y);
            Kt[(d + 33) * KSTR + key] = f2tf32(hi.y * cs1.x + lo.y * cs1.y);
            Kt[(d + 34) * KSTR + key] = f2tf32(hi.z * cs2.x + lo.z * cs2.y);
            Kt[(d + 35) * KSTR + key] = f2tf32(hi.w * cs3.x + lo.w * cs3.y);
        }
        // V: tf32 convert, float4 store (serial)
#pragma unroll
        for (int it = 0; it < 8; it++) {
            int i = tid + it * 128;
            int key = i >> 4, c4 = i & 15;
            float4 f = *(const float4*)(vp + (size_t)(kb + key) * 512 + c4 * 4);
            uint4 u;
            u.x = f2tf32(f.x); u.y = f2tf32(f.y);
            u.z = f2tf32(f.z); u.w = f2tf32(f.w);
            *(uint4*)&Vs[key * KSTR + c4 * 4] = u;
        }
        __syncthreads();

        // ---- S = Q @ K^T ----
        float sacc[8][4];
#pragma unroll
        for (int nf = 0; nf < 8; nf++)
#pragma unroll
            for (int c = 0; c < 4; c++) sacc[nf][c] = 0.f;
#pragma unroll
        for (int nf = 0; nf < 8; nf++) {
#pragma unroll
            for (int o = 0; o < 8; o++) {
                uint32_t bk[2];
                bk[0] = Kt[(o * 8 + tig) * KSTR + nf * 8 + gid];
                bk[1] = Kt[(o * 8 + tig + 4) * KSTR + nf * 8 + gid];
                mma_tf32(sacc[nf], aq[o], bk);
            }
        }

        // ---- causal mask on diagonal tile ----
        if (kt == qb) {
            int jr0 = w * 16 + gid, jr1 = jr0 + 8;
#pragma unroll
            for (int nf = 0; nf < 8; nf++) {
                int jc = nf * 8 + 2 * tig;
                if (jc > jr0)     sacc[nf][0] = -1e30f;
                if (jc + 1 > jr0) sacc[nf][1] = -1e30f;
                if (jc > jr1)     sacc[nf][2] = -1e30f;
                if (jc + 1 > jr1) sacc[nf][3] = -1e30f;
            }
        }

        // ---- online softmax (exp2 domain) ----
        float rx0 = -1e30f, rx1 = -1e30f;
#pragma unroll
        for (int nf = 0; nf < 8; nf++) {
            rx0 = fmaxf(rx0, fmaxf(sacc[nf][0], sacc[nf][1]));
            rx1 = fmaxf(rx1, fmaxf(sacc[nf][2], sacc[nf][3]));
        }
        rx0 = fmaxf(rx0, __shfl_xor_sync(0xffffffffu, rx0, 1));
        rx0 = fmaxf(rx0, __shfl_xor_sync(0xffffffffu, rx0, 2));
        rx1 = fmaxf(rx1, __shfl_xor_sync(0xffffffffu, rx1, 1));
        rx1 = fmaxf(rx1, __shfl_xor_sync(0xffffffffu, rx1, 2));
        float mn0 = fmaxf(m0, rx0), mn1 = fmaxf(m1, rx1);
        float corr0 = exp2f(m0 - mn0), corr1 = exp2f(m1 - mn1);
        m0 = mn0; m1 = mn1;
        float rs0 = 0.f, rs1 = 0.f;
#pragma unroll
        for (int nf = 0; nf < 8; nf++) {
            sacc[nf][0] = exp2f(sacc[nf][0] - m0);
            sacc[nf][1] = exp2f(sacc[nf][1] - m0);
            sacc[nf][2] = exp2f(sacc[nf][2] - m1);
            sacc[nf][3] = exp2f(sacc[nf][3] - m1);
            rs0 += sacc[nf][0] + sacc[nf][1];
            rs1 += sacc[nf][2] + sacc[nf][3];
        }
        rs0 += __shfl_xor_sync(0xffffffffu, rs0, 1);
        rs0 += __shfl_xor_sync(0xffffffffu, rs0, 2);
        rs1 += __shfl_xor_sync(0xffffffffu, rs1, 1);
        rs1 += __shfl_xor_sync(0xffffffffu, rs1, 2);
        l0 = l0 * corr0 + rs0;
        l1 = l1 * corr1 + rs1;
#pragma unroll
        for (int nf = 0; nf < 8; nf++) {
            oacc[nf][0] *= corr0; oacc[nf][1] *= corr0;
            oacc[nf][2] *= corr1; oacc[nf][3] *= corr1;
        }

        // ---- O += P @ V (C-layout -> A-layout via shuffles) ----
        const int srcA = (gid << 2) + (tig >> 1);
        const int srcB = srcA + 2;
        const bool odd = tig & 1;
#pragma unroll
        for (int ko = 0; ko < 8; ko++) {
            float s0a = __shfl_sync(0xffffffffu, sacc[ko][0], srcA);
            float s1a = __shfl_sync(0xffffffffu, sacc[ko][1], srcA);
            float s2a = __shfl_sync(0xffffffffu, sacc[ko][2], srcA);
            float s3a = __shfl_sync(0xffffffffu, sacc[ko][3], srcA);
            float s0b = __shfl_sync(0xffffffffu, sacc[ko][0], srcB);
            float s1b = __shfl_sync(0xffffffffu, sacc[ko][1], srcB);
            float s2b = __shfl_sync(0xffffffffu, sacc[ko][2], srcB);
            float s3b = __shfl_sync(0xffffffffu, sacc[ko][3], srcB);
            uint32_t pa[4];
            pa[0] = f2tf32(odd ? s1a : s0a);
            pa[1] = f2tf32(odd ? s3a : s2a);
            pa[2] = f2tf32(odd ? s1b : s0b);
            pa[3] = f2tf32(odd ? s3b : s2b);
#pragma unroll
            for (int nd = 0; nd < 8; nd++) {
                uint32_t bv[2];
                bv[0] = Vs[(ko * 8 + tig) * KSTR + nd * 8 + gid];
                bv[1] = Vs[(ko * 8 + tig + 4) * KSTR + nd * 8 + gid];
                mma_tf32(oacc[nd], pa, bv);
            }
        }
    }

    // ---- epilogue: write half ----
    float il0 = 1.f / l0, il1 = 1.f / l1;
    __half* y0 = y + (size_t)(b * TT + qb * 64 + w * 16 + gid) * 256 + h * 64;
    __half* y1 = y0 + (size_t)8 * 256;
#pragma unroll
    for (int nf = 0; nf < 8; nf++) {
        *(__half2*)(y0 + nf * 8 + 2 * tig) =
            __floats2half2_rn(oacc[nf][0] * il0, oacc[nf][1] * il0);
        *(__half2*)(y1 + nf * 8 + 2 * tig) =
            __floats2half2_rn(oacc[nf][2] * il1, oacc[nf][3] * il1);
    }
}

// ---------------------------------------------------------------------------
extern "C" void kernel_launch(void* const* d_in, const int* in_sizes, int n_in,
                              void* d_out, int out_size) {
    const float* x  = (const float*)d_in[0];
    const float* Wq = (const float*)d_in[1];
    const float* Wk = (const float*)d_in[2];
    const float* Wv = (const float*)d_in[3];
    const float* Wo = (const float*)d_in[4];
    float* out = (float*)d_out;

    float* qkv;
    __half* yh;
    float2* rt;
    cudaGetSymbolAddress((void**)&qkv, g_qkv);
    cudaGetSymbolAddress((void**)&yh, g_yh);
    cudaGetSymbolAddress((void**)&rt, g_rt);

    cudaFuncSetAttribute(hgemm_qkv_kernel,
                         cudaFuncAttributeMaxDynamicSharedMemorySize, HSMEM_BYTES);
    cudaFuncSetAttribute(hgemm_out_kernel,
                         cudaFuncAttributeMaxDynamicSharedMemorySize, HSMEM_BYTES);

    // rope table + input conversions
    rope_table_kernel<<<(TT * 32 + 255) / 256, 256>>>();
    cvt_x_kernel<<<(M_ROWS * 32 + 255) / 256, 256>>>(x);
    cvt_w_kernel<<<(196608 + 255) / 256, 256>>>(Wq, Wk, Wv, Wo);

    // fused QKV projection (fp16 tensor cores) -> qkv[M][512] (float)
    hgemm_qkv_kernel<<<dim3(4, M_ROWS / 128), 256, HSMEM_BYTES>>>(qkv);

    // tensor-core flash attention with fused rope -> yh[M][256] (half)
    {
        dim3 ga(TT / 64, NH, BB);
        attn_mma_kernel<<<ga, 128>>>(qkv, rt, yh);
    }

    // output projection (fp16 tensor cores)
    hgemm_out_kernel<<<dim3(2, M_ROWS / 128), 256, HSMEM_BYTES>>>(out);
}

// round 14
// speedup vs baseline: 1.8139x; 1.5860x over previous
#include <cuda_runtime.h>
#include <cuda_fp16.h>
#include <cstdint>
#include <math.h>

#define BB 128
#define TT 384
#define CC 256
#define NH 4
#define NKV 2
#define HD 64
#define M_ROWS (BB * TT)   // 49152

// ---------------- scratch (device globals; allocation is forbidden) --------
__device__ __align__(16) __half g_xh[(size_t)M_ROWS * 256];   // x in half
__device__ __align__(16) float  g_qkvf[(size_t)M_ROWS * 384]; // q(256)|k(128) float
__device__ __align__(16) __half g_qkh[(size_t)M_ROWS * 384];  // roped q|k half
__device__ __align__(16) __half g_vh[(size_t)M_ROWS * 128];   // v half
__device__ __align__(16) __half g_yh[(size_t)M_ROWS * CC];    // attn out half
__device__ __align__(16) __half g_wqt[256 * 256];             // W^T half [n][k]
__device__ __align__(16) __half g_wkt[128 * 256];
__device__ __align__(16) __half g_wvt[128 * 256];
__device__ __align__(16) __half g_wot[256 * 256];
__device__ float2 g_rt[TT * 32];                              // rope table

// ---------------- helpers ---------------------------------------------------
__device__ __forceinline__ uint32_t smem_u32(const void* p) {
    uint32_t a;
    asm("{ .reg .u64 t; cvta.to.shared.u64 t, %1; cvt.u32.u64 %0, t; }"
        : "=r"(a) : "l"(p));
    return a;
}
__device__ __forceinline__ void cp16(uint32_t s, const void* g) {
    asm volatile("cp.async.cg.shared.global [%0], [%1], 16;" :: "r"(s), "l"(g));
}
__device__ __forceinline__ void mma_f16(float* d, const uint32_t* a, const uint32_t* b) {
    asm volatile(
        "mma.sync.aligned.m16n8k16.row.col.f32.f16.f16.f32 "
        "{%0,%1,%2,%3}, {%4,%5,%6,%7}, {%8,%9}, {%0,%1,%2,%3};"
        : "+f"(d[0]), "+f"(d[1]), "+f"(d[2]), "+f"(d[3])
        : "r"(a[0]), "r"(a[1]), "r"(a[2]), "r"(a[3]), "r"(b[0]), "r"(b[1]));
}
__device__ __forceinline__ uint32_t packh2(float a, float b) {
    __half2 h = __floats2half2_rn(a, b);
    return *(uint32_t*)&h;
}

// ---------------------------------------------------------------------------
// Pre-convert kernels
// ---------------------------------------------------------------------------
__global__ void cvt_x_kernel(const float* __restrict__ x) {
    size_t j = (size_t)blockIdx.x * blockDim.x + threadIdx.x;   // 8 elems each
    if (j >= (size_t)M_ROWS * 32) return;
    const float4* xs = (const float4*)x;
    float4 f0 = xs[j * 2], f1 = xs[j * 2 + 1];
    uint4 u;
    u.x = packh2(f0.x, f0.y); u.y = packh2(f0.z, f0.w);
    u.z = packh2(f1.x, f1.y); u.w = packh2(f1.z, f1.w);
    ((uint4*)g_xh)[j] = u;
}

__global__ void cvt_w_kernel(const float* __restrict__ Wq, const float* __restrict__ Wk,
                             const float* __restrict__ Wv, const float* __restrict__ Wo) {
    int i = blockIdx.x * blockDim.x + threadIdx.x;
    if (i < 65536) {
        int n = i >> 8, k = i & 255;
        g_wqt[i] = __float2half(Wq[k * 256 + n]);
    } else if (i < 98304) {
        int i2 = i - 65536;
        int n = i2 >> 8, k = i2 & 255;
        g_wkt[i2] = __float2half(Wk[k * 128 + n]);
    } else if (i < 131072) {
        int i2 = i - 98304;
        int n = i2 >> 8, k = i2 & 255;
        g_wvt[i2] = __float2half(Wv[k * 128 + n]);
    } else if (i < 196608) {
        int i2 = i - 131072;
        int n = i2 >> 8, k = i2 & 255;
        g_wot[i2] = __float2half(Wo[k * 256 + n]);
    }
}

// ---------------------------------------------------------------------------
// fp16 m16n8k16 GEMM tile (proven in R13): C = Ah[128,256] @ Bt[n][k]^T.
// Output either float (Cf) or half (Ch).
// ---------------------------------------------------------------------------
#define HSTR 40
#define HOP_HALVES (128 * HSTR)
#define HSTAGE_HALVES (2 * HOP_HALVES)
#define HSMEM_BYTES (2 * HSTAGE_HALVES * 2)  // 40960

__device__ __forceinline__ void hgemm_tile_128(const __half* __restrict__ Ah,
                                               const __half* __restrict__ Bt,
                                               float* __restrict__ Cf,
                                               __half* __restrict__ Ch, int ldC) {
    extern __shared__ __half hsm[];
    const uint32_t sbase = smem_u32(hsm);

    const int tid  = threadIdx.x;
    const int warp = tid >> 5;
    const int lane = tid & 31;
    const int gid  = lane >> 2;
    const int tig  = lane & 3;
    const int warpM = (warp & 1) * 64;
    const int warpN = (warp >> 1) * 32;

    float acc[4][4][4];
#pragma unroll
    for (int mt = 0; mt < 4; mt++)
#pragma unroll
        for (int nt = 0; nt < 4; nt++)
#pragma unroll
            for (int r = 0; r < 4; r++) acc[mt][nt][r] = 0.f;

    auto load_stage = [&](int stage, int k0) {
        uint32_t sa = sbase + stage * (HSTAGE_HALVES * 2);
        uint32_t sb = sa + HOP_HALVES * 2;
#pragma unroll
        for (int i = 0; i < 2; i++) {
            int id = tid + i * 256;
            int row = id >> 2, c4 = id & 3;
            cp16(sa + row * 80 + c4 * 16, Ah + (size_t)row * 256 + k0 + c4 * 8);
            cp16(sb + row * 80 + c4 * 16, Bt + (size_t)row * 256 + k0 + c4 * 8);
        }
        asm volatile("cp.async.commit_group;" ::: "memory");
    };

    auto compute_stage = [&](int stage) {
        const __half* sa = hsm + stage * HSTAGE_HALVES;
        const __half* sb = sa + HOP_HALVES;
#pragma unroll
        for (int ks = 0; ks < 2; ks++) {
            const int kc = ks * 16;
            uint32_t bf[4][2];
#pragma unroll
            for (int nt = 0; nt < 4; nt++) {
                int n = warpN + nt * 8 + gid;
                bf[nt][0] = *(const uint32_t*)&sb[n * HSTR + kc + 2 * tig];
                bf[nt][1] = *(const uint32_t*)&sb[n * HSTR + kc + 8 + 2 * tig];
            }
#pragma unroll
            for (int mt = 0; mt < 4; mt++) {
                int r = warpM + mt * 16 + gid;
                uint32_t af[4];
                af[0] = *(const uint32_t*)&sa[r * HSTR + kc + 2 * tig];
                af[1] = *(const uint32_t*)&sa[(r + 8) * HSTR + kc + 2 * tig];
                af[2] = *(const uint32_t*)&sa[r * HSTR + kc + 8 + 2 * tig];
                af[3] = *(const uint32_t*)&sa[(r + 8) * HSTR + kc + 8 + 2 * tig];
#pragma unroll
                for (int nt = 0; nt < 4; nt++) mma_f16(acc[mt][nt], af, bf[nt]);
            }
        }
    };

    load_stage(0, 0);
#pragma unroll
    for (int it = 0; it < 8; it++) {
        if (it + 1 < 8) {
            load_stage((it + 1) & 1, (it + 1) * 32);
            asm volatile("cp.async.wait_group 1;" ::: "memory");
        } else {
            asm volatile("cp.async.wait_group 0;" ::: "memory");
        }
        __syncthreads();
        compute_stage(it & 1);
        __syncthreads();
    }

    if (Cf) {
#pragma unroll
        for (int mt = 0; mt < 4; mt++) {
            int row = warpM + mt * 16 + gid;
#pragma unroll
            for (int nt = 0; nt < 4; nt++) {
                int col = warpN + nt * 8 + tig * 2;
                *(float2*)(Cf + (size_t)row * ldC + col) =
                    make_float2(acc[mt][nt][0], acc[mt][nt][1]);
                *(float2*)(Cf + (size_t)(row + 8) * ldC + col) =
                    make_float2(acc[mt][nt][2], acc[mt][nt][3]);
            }
        }
    } else {
#pragma unroll
        for (int mt = 0; mt < 4; mt++) {
            int row = warpM + mt * 16 + gid;
#pragma unroll
            for (int nt = 0; nt < 4; nt++) {
                int col = warpN + nt * 8 + tig * 2;
                *(uint32_t*)(Ch + (size_t)row * ldC + col) =
                    packh2(acc[mt][nt][0], acc[mt][nt][1]);
                *(uint32_t*)(Ch + (size_t)(row + 8) * ldC + col) =
                    packh2(acc[mt][nt][2], acc[mt][nt][3]);
            }
        }
    }
}

// QKV: bx 0,1 -> q (float, g_qkvf cols 0..255); bx 2 -> k (float, cols 256..383);
// bx 3 -> v (half, g_vh).
__global__ void __launch_bounds__(256, 2)
hgemm_qkv_kernel() {
    const int bx = blockIdx.x, by = blockIdx.y;
    const __half* Ah = g_xh + (size_t)by * 128 * 256;
    if (bx < 2) {
        hgemm_tile_128(Ah, g_wqt + bx * 128 * 256,
                       g_qkvf + (size_t)by * 128 * 384 + bx * 128, nullptr, 384);
    } else if (bx == 2) {
        hgemm_tile_128(Ah, g_wkt,
                       g_qkvf + (size_t)by * 128 * 384 + 256, nullptr, 384);
    } else {
        hgemm_tile_128(Ah, g_wvt, nullptr,
                       g_vh + (size_t)by * 128 * 128, 128);
    }
}

__global__ void __launch_bounds__(256, 2)
hgemm_out_kernel(float* __restrict__ out) {
    const int bx = blockIdx.x, by = blockIdx.y;
    hgemm_tile_128(g_yh + (size_t)by * 128 * 256, g_wot + bx * 128 * 256,
                   out + (size_t)by * 128 * 256 + bx * 128, nullptr, 256);
}

// ---------------------------------------------------------------------------
// RoPE table
// ---------------------------------------------------------------------------
__global__ void rope_table_kernel() {
    int idx = blockIdx.x * blockDim.x + threadIdx.x;
    if (idx >= TT * 32) return;
    int t = idx >> 5, p = idx & 31;
    const float kLog2_10000_over32 = 0.41524101186407246f;
    float inv = exp2f(-(float)p * kLog2_10000_over32);
    float c, s;
    sincosf((float)t * inv, &s, &c);
    g_rt[idx] = make_float2(c, s);
}

// ---------------------------------------------------------------------------
// RoPE pass: read float q|k, rotate (table), write half. q additionally
// scaled by 0.125*log2e (exp2-domain softmax). Coalesced: p = lane.
// ---------------------------------------------------------------------------
__global__ void rope_half_kernel() {
    const float qscale = 0.18033688011112042f;
    int idx = blockIdx.x * blockDim.x + threadIdx.x;
    if (idx >= M_ROWS * 6 * 32) return;
    int p   = idx & 31;
    int rem = idx >> 5;
    int h6  = rem % 6;
    int row = rem / 6;
    int t = row % TT;
    int col = h6 * 64;            // q heads 0..3 at 0..255, k heads at 256..383
    float scale = (h6 < 4) ? qscale : 1.f;
    float2 cs = g_rt[t * 32 + p];
    const float* src = g_qkvf + (size_t)row * 384 + col;
    __half* dst = g_qkh + (size_t)row * 384 + col;
    float x1 = src[p], x2 = src[p + 32];
    dst[p]      = __float2half((x1 * cs.x - x2 * cs.y) * scale);
    dst[p + 32] = __float2half((x2 * cs.x + x1 * cs.y) * scale);
}

// ---------------------------------------------------------------------------
// fp16 tensor-core flash attention. Grid (T/64, H, B), 128 threads.
// Kh natural [key][d] (stride 72 halves), Vt transposed [d][key] (stride 72).
// S C-layout == PV A-layout (f16 k16) -> zero shuffles.
// ---------------------------------------------------------------------------
#define AST 72

__global__ void __launch_bounds__(128)
attn_mma_kernel() {
    __shared__ __half Kh[64 * AST];   // 9216 B (also stages Q initially)
    __shared__ __half Vt[64 * AST];

    const int qb = blockIdx.x;
    const int h  = blockIdx.y;
    const int b  = blockIdx.z;
    const int g  = h >> 1;
    const int tid = threadIdx.x;
    const int w = tid >> 5;
    const int lane = tid & 31;
    const int gid = lane >> 2;
    const int tig = lane & 3;
    const uint32_t sKh = smem_u32(Kh);

    const __half* qh = g_qkh + (size_t)(b * TT) * 384 + h * 64;
    const __half* kh = g_qkh + (size_t)(b * TT) * 384 + 256 + g * 64;
    const __half* vh = g_vh + (size_t)(b * TT) * 128 + g * 64;

    // ---- stage Q (already roped+scaled) into Kh, extract A-frags ----
#pragma unroll
    for (int it = 0; it < 4; it++) {
        int i = tid + it * 128;          // 0..511
        int r = i >> 3, c8 = i & 7;
        *(uint4*)&Kh[r * AST + c8 * 8] =
            *(const uint4*)(qh + (size_t)(qb * 64 + r) * 384 + c8 * 8);
    }
    __syncthreads();
    uint32_t aq[4][4];
    {
        int r0 = w * 16 + gid;
#pragma unroll
        for (int o = 0; o < 4; o++) {
            aq[o][0] = *(const uint32_t*)&Kh[r0 * AST + o * 16 + 2 * tig];
            aq[o][1] = *(const uint32_t*)&Kh[(r0 + 8) * AST + o * 16 + 2 * tig];
            aq[o][2] = *(const uint32_t*)&Kh[r0 * AST + o * 16 + 8 + 2 * tig];
            aq[o][3] = *(const uint32_t*)&Kh[(r0 + 8) * AST + o * 16 + 8 + 2 * tig];
        }
    }

    float m0 = -1e30f, m1 = -1e30f, l0 = 0.f, l1 = 0.f;
    float oacc[8][4];
#pragma unroll
    for (int nf = 0; nf < 8; nf++)
#pragma unroll
        for (int c = 0; c < 4; c++) oacc[nf][c] = 0.f;

    for (int kt = 0; kt <= qb; kt++) {
        const int kb = kt * 64;
        __syncthreads();   // prior tile's reads (and Q extraction) done

        // K: pure copy via cp.async (natural [key][d])
#pragma unroll
        for (int it = 0; it < 4; it++) {
            int i = tid + it * 128;
            int key = i >> 3, c8 = i & 7;
            cp16(sKh + (key * AST + c8 * 8) * 2,
                 kh + (size_t)(kb + key) * 384 + c8 * 8);
        }
        asm volatile("cp.async.commit_group;" ::: "memory");
        // V: transpose-store [d][key]
#pragma unroll
        for (int it = 0; it < 4; it++) {
            int i = tid + it * 128;
            int key = i & 63, d8 = i >> 6;
            uint4 v = *(const uint4*)(vh + (size_t)(kb + key) * 128 + d8 * 8);
            const __half* hp = (const __half*)&v;
#pragma unroll
            for (int j = 0; j < 8; j++)
                Vt[(d8 * 8 + j) * AST + key] = hp[j];
        }
        asm volatile("cp.async.wait_group 0;" ::: "memory");
        __syncthreads();

        // ---- S = Q @ K^T (f16 k16) ----
        float sacc[8][4];
#pragma unroll
        for (int nf = 0; nf < 8; nf++)
#pragma unroll
            for (int c = 0; c < 4; c++) sacc[nf][c] = 0.f;
#pragma unroll
        for (int nf = 0; nf < 8; nf++) {
#pragma unroll
            for (int o = 0; o < 4; o++) {
                uint32_t bk[2];
                bk[0] = *(const uint32_t*)&Kh[(nf * 8 + gid) * AST + o * 16 + 2 * tig];
                bk[1] = *(const uint32_t*)&Kh[(nf * 8 + gid) * AST + o * 16 + 8 + 2 * tig];
                mma_f16(sacc[nf], aq[o], bk);
            }
        }

        // ---- causal mask on diagonal tile ----
        if (kt == qb) {
            int jr0 = w * 16 + gid, jr1 = jr0 + 8;
#pragma unroll
            for (int nf = 0; nf < 8; nf++) {
                int jc = nf * 8 + 2 * tig;
                if (jc > jr0)     sacc[nf][0] = -1e30f;
                if (jc + 1 > jr0) sacc[nf][1] = -1e30f;
                if (jc > jr1)     sacc[nf][2] = -1e30f;
                if (jc + 1 > jr1) sacc[nf][3] = -1e30f;
            }
        }

        // ---- online softmax (exp2 domain) ----
        float rx0 = -1e30f, rx1 = -1e30f;
#pragma unroll
        for (int nf = 0; nf < 8; nf++) {
            rx0 = fmaxf(rx0, fmaxf(sacc[nf][0], sacc[nf][1]));
            rx1 = fmaxf(rx1, fmaxf(sacc[nf][2], sacc[nf][3]));
        }
        rx0 = fmaxf(rx0, __shfl_xor_sync(0xffffffffu, rx0, 1));
        rx0 = fmaxf(rx0, __shfl_xor_sync(0xffffffffu, rx0, 2));
        rx1 = fmaxf(rx1, __shfl_xor_sync(0xffffffffu, rx1, 1));
        rx1 = fmaxf(rx1, __shfl_xor_sync(0xffffffffu, rx1, 2));
        float mn0 = fmaxf(m0, rx0), mn1 = fmaxf(m1, rx1);
        float corr0 = exp2f(m0 - mn0), corr1 = exp2f(m1 - mn1);
        m0 = mn0; m1 = mn1;
        float rs0 = 0.f, rs1 = 0.f;
#pragma unroll
        for (int nf = 0; nf < 8; nf++) {
            sacc[nf][0] = exp2f(sacc[nf][0] - m0);
            sacc[nf][1] = exp2f(sacc[nf][1] - m0);
            sacc[nf][2] = exp2f(sacc[nf][2] - m1);
            sacc[nf][3] = exp2f(sacc[nf][3] - m1);
            rs0 += sacc[nf][0] + sacc[nf][1];
            rs1 += sacc[nf][2] + sacc[nf][3];
        }
        rs0 += __shfl_xor_sync(0xffffffffu, rs0, 1);
        rs0 += __shfl_xor_sync(0xffffffffu, rs0, 2);
        rs1 += __shfl_xor_sync(0xffffffffu, rs1, 1);
        rs1 += __shfl_xor_sync(0xffffffffu, rs1, 2);
        l0 = l0 * corr0 + rs0;
        l1 = l1 * corr1 + rs1;
#pragma unroll
        for (int nf = 0; nf < 8; nf++) {
            oacc[nf][0] *= corr0; oacc[nf][1] *= corr0;
            oacc[nf][2] *= corr1; oacc[nf][3] *= corr1;
        }

        // ---- O += P @ V : S C-layout IS the f16 A-layout (no shuffles) ----
#pragma unroll
        for (int ko = 0; ko < 4; ko++) {
            uint32_t pa[4];
            pa[0] = packh2(sacc[2 * ko][0], sacc[2 * ko][1]);
            pa[1] = packh2(sacc[2 * ko][2], sacc[2 * ko][3]);
            pa[2] = packh2(sacc[2 * ko + 1][0], sacc[2 * ko + 1][1]);
            pa[3] = packh2(sacc[2 * ko + 1][2], sacc[2 * ko + 1][3]);
#pragma unroll
            for (int nd = 0; nd < 8; nd++) {
                uint32_t bv[2];
                bv[0] = *(const uint32_t*)&Vt[(nd * 8 + gid) * AST + ko * 16 + 2 * tig];
                bv[1] = *(const uint32_t*)&Vt[(nd * 8 + gid) * AST + ko * 16 + 8 + 2 * tig];
                mma_f16(oacc[nd], pa, bv);
            }
        }
    }

    // ---- epilogue: write half ----
    float il0 = 1.f / l0, il1 = 1.f / l1;
    __half* y0 = g_yh + (size_t)(b * TT + qb * 64 + w * 16 + gid) * 256 + h * 64;
    __half* y1 = y0 + (size_t)8 * 256;
#pragma unroll
    for (int nf = 0; nf < 8; nf++) {
        *(uint32_t*)(y0 + nf * 8 + 2 * tig) =
            packh2(oacc[nf][0] * il0, oacc[nf][1] * il0);
        *(uint32_t*)(y1 + nf * 8 + 2 * tig) =
            packh2(oacc[nf][2] * il1, oacc[nf][3] * il1);
    }
}

// ---------------------------------------------------------------------------
extern "C" void kernel_launch(void* const* d_in, const int* in_sizes, int n_in,
                              void* d_out, int out_size) {
    const float* x  = (const float*)d_in[0];
    const float* Wq = (const float*)d_in[1];
    const float* Wk = (const float*)d_in[2];
    const float* Wv = (const float*)d_in[3];
    const float* Wo = (const float*)d_in[4];
    float* out = (float*)d_out;

    cudaFuncSetAttribute(hgemm_qkv_kernel,
                         cudaFuncAttributeMaxDynamicSharedMemorySize, HSMEM_BYTES);
    cudaFuncSetAttribute(hgemm_out_kernel,
                         cudaFuncAttributeMaxDynamicSharedMemorySize, HSMEM_BYTES);

    rope_table_kernel<<<(TT * 32 + 255) / 256, 256>>>();
    cvt_x_kernel<<<(M_ROWS * 32 + 255) / 256, 256>>>(x);
    cvt_w_kernel<<<(196608 + 255) / 256, 256>>>(Wq, Wk, Wv, Wo);

    // QKV projection: q,k float -> g_qkvf; v half -> g_vh
    hgemm_qkv_kernel<<<dim3(4, M_ROWS / 128), 256, HSMEM_BYTES>>>();

    // rope + downconvert q,k -> g_qkh (half), q pre-scaled
    rope_half_kernel<<<(M_ROWS * 6 * 32 + 255) / 256, 256>>>();

    // fp16 flash attention -> g_yh
    {
        dim3 ga(TT / 64, NH, BB);
        attn_mma_kernel<<<ga, 128>>>();
    }

    // output projection
    hgemm_out_kernel<<<dim3(2, M_ROWS / 128), 256, HSMEM_BYTES>>>(out);
}

// round 15
// speedup vs baseline: 2.0435x; 1.1265x over previous
#include <cuda_runtime.h>
#include <cuda_fp16.h>
#include <cstdint>
#include <math.h>

#define BB 128
#define TT 384
#define CC 256
#define NH 4
#define NKV 2
#define HD 64
#define M_ROWS (BB * TT)   // 49152

// ---------------- scratch (device globals; allocation is forbidden) --------
__device__ __align__(16) __half g_xh[(size_t)M_ROWS * 256];   // x in half
__device__ __align__(16) __half g_qkh[(size_t)M_ROWS * 384];  // roped q|k half
__device__ __align__(16) __half g_vh[(size_t)M_ROWS * 128];   // v half
__device__ __align__(16) __half g_yh[(size_t)M_ROWS * CC];    // attn out half
__device__ __align__(16) __half g_wqt[256 * 256];             // W^T half [n][k]
__device__ __align__(16) __half g_wkt[128 * 256];
__device__ __align__(16) __half g_wvt[128 * 256];
__device__ __align__(16) __half g_wot[256 * 256];
__device__ float2 g_rt[TT * 32];                              // rope table

// ---------------- helpers ---------------------------------------------------
__device__ __forceinline__ uint32_t smem_u32(const void* p) {
    uint32_t a;
    asm("{ .reg .u64 t; cvta.to.shared.u64 t, %1; cvt.u32.u64 %0, t; }"
        : "=r"(a) : "l"(p));
    return a;
}
__device__ __forceinline__ void cp16(uint32_t s, const void* g) {
    asm volatile("cp.async.cg.shared.global [%0], [%1], 16;" :: "r"(s), "l"(g));
}
__device__ __forceinline__ void mma_f16(float* d, const uint32_t* a, const uint32_t* b) {
    asm volatile(
        "mma.sync.aligned.m16n8k16.row.col.f32.f16.f16.f32 "
        "{%0,%1,%2,%3}, {%4,%5,%6,%7}, {%8,%9}, {%0,%1,%2,%3};"
        : "+f"(d[0]), "+f"(d[1]), "+f"(d[2]), "+f"(d[3])
        : "r"(a[0]), "r"(a[1]), "r"(a[2]), "r"(a[3]), "r"(b[0]), "r"(b[1]));
}
__device__ __forceinline__ uint32_t packh2(float a, float b) {
    __half2 h = __floats2half2_rn(a, b);
    return *(uint32_t*)&h;
}

// ---------------------------------------------------------------------------
// Pre-convert kernels
// ---------------------------------------------------------------------------
__global__ void cvt_x_kernel(const float* __restrict__ x) {
    size_t j = (size_t)blockIdx.x * blockDim.x + threadIdx.x;   // 8 elems each
    if (j >= (size_t)M_ROWS * 32) return;
    const float4* xs = (const float4*)x;
    float4 f0 = xs[j * 2], f1 = xs[j * 2 + 1];
    uint4 u;
    u.x = packh2(f0.x, f0.y); u.y = packh2(f0.z, f0.w);
    u.z = packh2(f1.x, f1.y); u.w = packh2(f1.z, f1.w);
    ((uint4*)g_xh)[j] = u;
}

__global__ void cvt_w_kernel(const float* __restrict__ Wq, const float* __restrict__ Wk,
                             const float* __restrict__ Wv, const float* __restrict__ Wo) {
    int i = blockIdx.x * blockDim.x + threadIdx.x;
    if (i < 65536) {
        int n = i >> 8, k = i & 255;
        g_wqt[i] = __float2half(Wq[k * 256 + n]);
    } else if (i < 98304) {
        int i2 = i - 65536;
        int n = i2 >> 8, k = i2 & 255;
        g_wkt[i2] = __float2half(Wk[k * 128 + n]);
    } else if (i < 131072) {
        int i2 = i - 98304;
        int n = i2 >> 8, k = i2 & 255;
        g_wvt[i2] = __float2half(Wv[k * 128 + n]);
    } else if (i < 196608) {
        int i2 = i - 131072;
        int n = i2 >> 8, k = i2 & 255;
        g_wot[i2] = __float2half(Wo[k * 256 + n]);
    }
}

// ---------------------------------------------------------------------------
// RoPE table
// ---------------------------------------------------------------------------
__global__ void rope_table_kernel() {
    int idx = blockIdx.x * blockDim.x + threadIdx.x;
    if (idx >= TT * 32) return;
    int t = idx >> 5, p = idx & 31;
    const float kLog2_10000_over32 = 0.41524101186407246f;
    float inv = exp2f(-(float)p * kLog2_10000_over32);
    float c, s;
    sincosf((float)t * inv, &s, &c);
    g_rt[idx] = make_float2(c, s);
}

// ---------------------------------------------------------------------------
// fp16 m16n8k16 GEMM tile, 3-stage cp.async ring, warp tile 32x64
// (warpM=(w>>1)*32, warpN=(w&1)*64) so rope pairs (p, p+32) are
// register-local (nt and nt+4). One __syncthreads per iteration.
// MODE 0: float out. MODE 1: half out. MODE 2: rope(+scale) half out.
// ---------------------------------------------------------------------------
#define HSTR 40
#define HOP_HALVES (128 * HSTR)            // 5120
#define HSTAGE_HALVES (2 * HOP_HALVES)     // 10240 (20480 B)
#define HSMEM_BYTES (3 * HSTAGE_HALVES * 2)  // 61440

template <int MODE>
__device__ __forceinline__ void hgemm_tile_128(const __half* __restrict__ Ah,
                                               const __half* __restrict__ Bt,
                                               float* __restrict__ Cf,
                                               __half* __restrict__ Ch,
                                               int ldC, int rowbase, float scale) {
    extern __shared__ __half hsm[];
    const uint32_t sbase = smem_u32(hsm);

    const int tid  = threadIdx.x;
    const int warp = tid >> 5;
    const int lane = tid & 31;
    const int gid  = lane >> 2;
    const int tig  = lane & 3;
    const int warpM = (warp >> 1) * 32;
    const int warpN = (warp & 1) * 64;

    float acc[2][8][4];
#pragma unroll
    for (int mt = 0; mt < 2; mt++)
#pragma unroll
        for (int nt = 0; nt < 8; nt++)
#pragma unroll
            for (int r = 0; r < 4; r++) acc[mt][nt][r] = 0.f;

    auto load_stage = [&](int stage, int k0) {
        uint32_t sa = sbase + stage * (HSTAGE_HALVES * 2);
        uint32_t sb = sa + HOP_HALVES * 2;
#pragma unroll
        for (int i = 0; i < 2; i++) {
            int id = tid + i * 256;
            int row = id >> 2, c4 = id & 3;
            cp16(sa + row * 80 + c4 * 16, Ah + (size_t)row * 256 + k0 + c4 * 8);
            cp16(sb + row * 80 + c4 * 16, Bt + (size_t)row * 256 + k0 + c4 * 8);
        }
        asm volatile("cp.async.commit_group;" ::: "memory");
    };

    auto compute_stage = [&](int stage) {
        const __half* sa = hsm + stage * HSTAGE_HALVES;
        const __half* sb = sa + HOP_HALVES;
#pragma unroll
        for (int ks = 0; ks < 2; ks++) {
            const int kc = ks * 16;
            uint32_t bf[8][2];
#pragma unroll
            for (int nt = 0; nt < 8; nt++) {
                int n = warpN + nt * 8 + gid;
                bf[nt][0] = *(const uint32_t*)&sb[n * HSTR + kc + 2 * tig];
                bf[nt][1] = *(const uint32_t*)&sb[n * HSTR + kc + 8 + 2 * tig];
            }
#pragma unroll
            for (int mt = 0; mt < 2; mt++) {
                int r = warpM + mt * 16 + gid;
                uint32_t af[4];
                af[0] = *(const uint32_t*)&sa[r * HSTR + kc + 2 * tig];
                af[1] = *(const uint32_t*)&sa[(r + 8) * HSTR + kc + 2 * tig];
                af[2] = *(const uint32_t*)&sa[r * HSTR + kc + 8 + 2 * tig];
                af[3] = *(const uint32_t*)&sa[(r + 8) * HSTR + kc + 8 + 2 * tig];
#pragma unroll
                for (int nt = 0; nt < 8; nt++) mma_f16(acc[mt][nt], af, bf[nt]);
            }
        }
    };

    // 3-stage ring, one sync per iteration
    load_stage(0, 0);
    load_stage(1, 32);
#pragma unroll
    for (int it = 0; it < 8; it++) {
        if (it < 7) {
            asm volatile("cp.async.wait_group 1;" ::: "memory");
        } else {
            asm volatile("cp.async.wait_group 0;" ::: "memory");
        }
        __syncthreads();
        if (it + 2 < 8) load_stage((it + 2) % 3, (it + 2) * 32);
        compute_stage(it % 3);
    }

    // ---- epilogue ----
    if (MODE == 0) {
#pragma unroll
        for (int mt = 0; mt < 2; mt++) {
            int row = rowbase + warpM + mt * 16 + gid;
#pragma unroll
            for (int nt = 0; nt < 8; nt++) {
                int col = warpN + nt * 8 + tig * 2;
                *(float2*)(Cf + (size_t)row * ldC + col) =
                    make_float2(acc[mt][nt][0], acc[mt][nt][1]);
                *(float2*)(Cf + (size_t)(row + 8) * ldC + col) =
                    make_float2(acc[mt][nt][2], acc[mt][nt][3]);
            }
        }
    } else if (MODE == 1) {
#pragma unroll
        for (int mt = 0; mt < 2; mt++) {
            int row = rowbase + warpM + mt * 16 + gid;
#pragma unroll
            for (int nt = 0; nt < 8; nt++) {
                int col = warpN + nt * 8 + tig * 2;
                *(uint32_t*)(Ch + (size_t)row * ldC + col) =
                    packh2(acc[mt][nt][0], acc[mt][nt][1]);
                *(uint32_t*)(Ch + (size_t)(row + 8) * ldC + col) =
                    packh2(acc[mt][nt][2], acc[mt][nt][3]);
            }
        }
    } else {
        // rope: pair (p, p+32) = (nt, nt+4), register-local
#pragma unroll
        for (int mt = 0; mt < 2; mt++) {
            int r0 = warpM + mt * 16 + gid;
#pragma unroll
            for (int nt = 0; nt < 4; nt++) {
                int p = nt * 8 + 2 * tig;
#pragma unroll
                for (int cp = 0; cp < 2; cp++) {
                    int row = rowbase + r0 + cp * 8;
                    int t = row % TT;
                    float2 cs0 = g_rt[t * 32 + p];
                    float2 cs1 = g_rt[t * 32 + p + 1];
                    float v1a = acc[mt][nt][cp * 2 + 0];
                    float v1b = acc[mt][nt][cp * 2 + 1];
                    float v2a = acc[mt][nt + 4][cp * 2 + 0];
                    float v2b = acc[mt][nt + 4][cp * 2 + 1];
                    __half* base = Ch + (size_t)row * ldC + warpN + p;
                    *(uint32_t*)base =
                        packh2((v1a * cs0.x - v2a * cs0.y) * scale,
                               (v1b * cs1.x - v2b * cs1.y) * scale);
                    *(uint32_t*)(base + 32) =
                        packh2((v2a * cs0.x + v1a * cs0.y) * scale,
                               (v2b * cs1.x + v1b * cs1.y) * scale);
                }
            }
        }
    }
}

// QKV: bx 0,1 -> q (rope+scale, half); bx 2 -> k (rope, half); bx 3 -> v (half)
__global__ void __launch_bounds__(256, 2)
hgemm_qkv_kernel() {
    const float qscale = 0.18033688011112042f;  // 0.125 * log2(e)
    const int bx = blockIdx.x, by = blockIdx.y;
    const __half* Ah = g_xh + (size_t)by * 128 * 256;
    if (bx < 2) {
        hgemm_tile_128<2>(Ah, g_wqt + bx * 128 * 256, nullptr,
                          g_qkh + bx * 128, 384, by * 128, qscale);
    } else if (bx == 2) {
        hgemm_tile_128<2>(Ah, g_wkt, nullptr,
                          g_qkh + 256, 384, by * 128, 1.f);
    } else {
        hgemm_tile_128<1>(Ah, g_wvt, nullptr, g_vh, 128, by * 128, 1.f);
    }
}

__global__ void __launch_bounds__(256, 2)
hgemm_out_kernel(float* __restrict__ out) {
    const int bx = blockIdx.x, by = blockIdx.y;
    hgemm_tile_128<0>(g_yh + (size_t)by * 128 * 256, g_wot + bx * 128 * 256,
                      out + bx * 128, nullptr, 256, by * 128, 1.f);
}

// ---------------------------------------------------------------------------
// fp16 tensor-core flash attention (unchanged from R14, measured-good).
// ---------------------------------------------------------------------------
#define AST 72

__global__ void __launch_bounds__(128)
attn_mma_kernel() {
    __shared__ __half Kh[64 * AST];
    __shared__ __half Vt[64 * AST];

    const int qb = blockIdx.x;
    const int h  = blockIdx.y;
    const int b  = blockIdx.z;
    const int g  = h >> 1;
    const int tid = threadIdx.x;
    const int w = tid >> 5;
    const int lane = tid & 31;
    const int gid = lane >> 2;
    const int tig = lane & 3;
    const uint32_t sKh = smem_u32(Kh);

    const __half* qh = g_qkh + (size_t)(b * TT) * 384 + h * 64;
    const __half* kh = g_qkh + (size_t)(b * TT) * 384 + 256 + g * 64;
    const __half* vh = g_vh + (size_t)(b * TT) * 128 + g * 64;

#pragma unroll
    for (int it = 0; it < 4; it++) {
        int i = tid + it * 128;
        int r = i >> 3, c8 = i & 7;
        *(uint4*)&Kh[r * AST + c8 * 8] =
            *(const uint4*)(qh + (size_t)(qb * 64 + r) * 384 + c8 * 8);
    }
    __syncthreads();
    uint32_t aq[4][4];
    {
        int r0 = w * 16 + gid;
#pragma unroll
        for (int o = 0; o < 4; o++) {
            aq[o][0] = *(const uint32_t*)&Kh[r0 * AST + o * 16 + 2 * tig];
            aq[o][1] = *(const uint32_t*)&Kh[(r0 + 8) * AST + o * 16 + 2 * tig];
            aq[o][2] = *(const uint32_t*)&Kh[r0 * AST + o * 16 + 8 + 2 * tig];
            aq[o][3] = *(const uint32_t*)&Kh[(r0 + 8) * AST + o * 16 + 8 + 2 * tig];
        }
    }

    float m0 = -1e30f, m1 = -1e30f, l0 = 0.f, l1 = 0.f;
    float oacc[8][4];
#pragma unroll
    for (int nf = 0; nf < 8; nf++)
#pragma unroll
        for (int c = 0; c < 4; c++) oacc[nf][c] = 0.f;

    for (int kt = 0; kt <= qb; kt++) {
        const int kb = kt * 64;
        __syncthreads();

#pragma unroll
        for (int it = 0; it < 4; it++) {
            int i = tid + it * 128;
            int key = i >> 3, c8 = i & 7;
            cp16(sKh + (key * AST + c8 * 8) * 2,
                 kh + (size_t)(kb + key) * 384 + c8 * 8);
        }
        asm volatile("cp.async.commit_group;" ::: "memory");
#pragma unroll
        for (int it = 0; it < 4; it++) {
            int i = tid + it * 128;
            int key = i & 63, d8 = i >> 6;
            uint4 v = *(const uint4*)(vh + (size_t)(kb + key) * 128 + d8 * 8);
            const __half* hp = (const __half*)&v;
#pragma unroll
            for (int j = 0; j < 8; j++)
                Vt[(d8 * 8 + j) * AST + key] = hp[j];
        }
        asm volatile("cp.async.wait_group 0;" ::: "memory");
        __syncthreads();

        float sacc[8][4];
#pragma unroll
        for (int nf = 0; nf < 8; nf++)
#pragma unroll
            for (int c = 0; c < 4; c++) sacc[nf][c] = 0.f;
#pragma unroll
        for (int nf = 0; nf < 8; nf++) {
#pragma unroll
            for (int o = 0; o < 4; o++) {
                uint32_t bk[2];
                bk[0] = *(const uint32_t*)&Kh[(nf * 8 + gid) * AST + o * 16 + 2 * tig];
                bk[1] = *(const uint32_t*)&Kh[(nf * 8 + gid) * AST + o * 16 + 8 + 2 * tig];
                mma_f16(sacc[nf], aq[o], bk);
            }
        }

        if (kt == qb) {
            int jr0 = w * 16 + gid, jr1 = jr0 + 8;
#pragma unroll
            for (int nf = 0; nf < 8; nf++) {
                int jc = nf * 8 + 2 * tig;
                if (jc > jr0)     sacc[nf][0] = -1e30f;
                if (jc + 1 > jr0) sacc[nf][1] = -1e30f;
                if (jc > jr1)     sacc[nf][2] = -1e30f;
                if (jc + 1 > jr1) sacc[nf][3] = -1e30f;
            }
        }

        float rx0 = -1e30f, rx1 = -1e30f;
#pragma unroll
        for (int nf = 0; nf < 8; nf++) {
            rx0 = fmaxf(rx0, fmaxf(sacc[nf][0], sacc[nf][1]));
            rx1 = fmaxf(rx1, fmaxf(sacc[nf][2], sacc[nf][3]));
        }
        rx0 = fmaxf(rx0, __shfl_xor_sync(0xffffffffu, rx0, 1));
        rx0 = fmaxf(rx0, __shfl_xor_sync(0xffffffffu, rx0, 2));
        rx1 = fmaxf(rx1, __shfl_xor_sync(0xffffffffu, rx1, 1));
        rx1 = fmaxf(rx1, __shfl_xor_sync(0xffffffffu, rx1, 2));
        float mn0 = fmaxf(m0, rx0), mn1 = fmaxf(m1, rx1);
        float corr0 = exp2f(m0 - mn0), corr1 = exp2f(m1 - mn1);
        m0 = mn0; m1 = mn1;
        float rs0 = 0.f, rs1 = 0.f;
#pragma unroll
        for (int nf = 0; nf < 8; nf++) {
            sacc[nf][0] = exp2f(sacc[nf][0] - m0);
            sacc[nf][1] = exp2f(sacc[nf][1] - m0);
            sacc[nf][2] = exp2f(sacc[nf][2] - m1);
            sacc[nf][3] = exp2f(sacc[nf][3] - m1);
            rs0 += sacc[nf][0] + sacc[nf][1];
            rs1 += sacc[nf][2] + sacc[nf][3];
        }
        rs0 += __shfl_xor_sync(0xffffffffu, rs0, 1);
        rs0 += __shfl_xor_sync(0xffffffffu, rs0, 2);
        rs1 += __shfl_xor_sync(0xffffffffu, rs1, 1);
        rs1 += __shfl_xor_sync(0xffffffffu, rs1, 2);
        l0 = l0 * corr0 + rs0;
        l1 = l1 * corr1 + rs1;
#pragma unroll
        for (int nf = 0; nf < 8; nf++) {
            oacc[nf][0] *= corr0; oacc[nf][1] *= corr0;
            oacc[nf][2] *= corr1; oacc[nf][3] *= corr1;
        }

#pragma unroll
        for (int ko = 0; ko < 4; ko++) {
            uint32_t pa[4];
            pa[0] = packh2(sacc[2 * ko][0], sacc[2 * ko][1]);
            pa[1] = packh2(sacc[2 * ko][2], sacc[2 * ko][3]);
            pa[2] = packh2(sacc[2 * ko + 1][0], sacc[2 * ko + 1][1]);
            pa[3] = packh2(sacc[2 * ko + 1][2], sacc[2 * ko + 1][3]);
#pragma unroll
            for (int nd = 0; nd < 8; nd++) {
                uint32_t bv[2];
                bv[0] = *(const uint32_t*)&Vt[(nd * 8 + gid) * AST + ko * 16 + 2 * tig];
                bv[1] = *(const uint32_t*)&Vt[(nd * 8 + gid) * AST + ko * 16 + 8 + 2 * tig];
                mma_f16(oacc[nd], pa, bv);
            }
        }
    }

    float il0 = 1.f / l0, il1 = 1.f / l1;
    __half* y0 = g_yh + (size_t)(b * TT + qb * 64 + w * 16 + gid) * 256 + h * 64;
    __half* y1 = y0 + (size_t)8 * 256;
#pragma unroll
    for (int nf = 0; nf < 8; nf++) {
        *(uint32_t*)(y0 + nf * 8 + 2 * tig) =
            packh2(oacc[nf][0] * il0, oacc[nf][1] * il0);
        *(uint32_t*)(y1 + nf * 8 + 2 * tig) =
            packh2(oacc[nf][2] * il1, oacc[nf][3] * il1);
    }
}

// ---------------------------------------------------------------------------
extern "C" void kernel_launch(void* const* d_in, const int* in_sizes, int n_in,
                              void* d_out, int out_size) {
    const float* x  = (const float*)d_in[0];
    const float* Wq = (const float*)d_in[1];
    const float* Wk = (const float*)d_in[2];
    const float* Wv = (const float*)d_in[3];
    const float* Wo = (const float*)d_in[4];
    float* out = (float*)d_out;

    cudaFuncSetAttribute(hgemm_qkv_kernel,
                         cudaFuncAttributeMaxDynamicSharedMemorySize, HSMEM_BYTES);
    cudaFuncSetAttribute(hgemm_out_kernel,
                         cudaFuncAttributeMaxDynamicSharedMemorySize, HSMEM_BYTES);

    rope_table_kernel<<<(TT * 32 + 255) / 256, 256>>>();
    cvt_x_kernel<<<(M_ROWS * 32 + 255) / 256, 256>>>(x);
    cvt_w_kernel<<<(196608 + 255) / 256, 256>>>(Wq, Wk, Wv, Wo);

    // QKV projection with fused rope epilogue -> g_qkh (half), g_vh (half)
    hgemm_qkv_kernel<<<dim3(4, M_ROWS / 128), 256, HSMEM_BYTES>>>();

    // fp16 flash attention -> g_yh
    {
        dim3 ga(TT / 64, NH, BB);
        attn_mma_kernel<<<ga, 128>>>();
    }

    // output projection
    hgemm_out_kernel<<<dim3(2, M_ROWS / 128), 256, HSMEM_BYTES>>>(out);
}

// round 16
// speedup vs baseline: 2.0901x; 1.0228x over previous
#include <cuda_runtime.h>
#include <cuda_fp16.h>
#include <cstdint>
#include <math.h>

#define BB 128
#define TT 384
#define CC 256
#define NH 4
#define NKV 2
#define HD 64
#define M_ROWS (BB * TT)   // 49152

// ---------------- scratch (device globals; allocation is forbidden) --------
__device__ __align__(16) __half g_xh[(size_t)M_ROWS * 256];   // x in half
__device__ __align__(16) __half g_qkh[(size_t)M_ROWS * 384];  // roped q|k half
__device__ __align__(16) __half g_vh[(size_t)M_ROWS * 128];   // v half
__device__ __align__(16) __half g_yh[(size_t)M_ROWS * CC];    // attn out half
__device__ __align__(16) __half g_wqt[256 * 256];             // W^T half [n][k]
__device__ __align__(16) __half g_wkt[128 * 256];
__device__ __align__(16) __half g_wvt[128 * 256];
__device__ __align__(16) __half g_wot[256 * 256];
__device__ float2 g_rt[TT * 32];                              // rope table

// ---------------- helpers ---------------------------------------------------
__device__ __forceinline__ uint32_t smem_u32(const void* p) {
    uint32_t a;
    asm("{ .reg .u64 t; cvta.to.shared.u64 t, %1; cvt.u32.u64 %0, t; }"
        : "=r"(a) : "l"(p));
    return a;
}
__device__ __forceinline__ void cp16(uint32_t s, const void* g) {
    asm volatile("cp.async.cg.shared.global [%0], [%1], 16;" :: "r"(s), "l"(g));
}
__device__ __forceinline__ void mma_f16(float* d, const uint32_t* a, const uint32_t* b) {
    asm volatile(
        "mma.sync.aligned.m16n8k16.row.col.f32.f16.f16.f32 "
        "{%0,%1,%2,%3}, {%4,%5,%6,%7}, {%8,%9}, {%0,%1,%2,%3};"
        : "+f"(d[0]), "+f"(d[1]), "+f"(d[2]), "+f"(d[3])
        : "r"(a[0]), "r"(a[1]), "r"(a[2]), "r"(a[3]), "r"(b[0]), "r"(b[1]));
}
__device__ __forceinline__ uint32_t packh2(float a, float b) {
    __half2 h = __floats2half2_rn(a, b);
    return *(uint32_t*)&h;
}

// ---------------------------------------------------------------------------
// Pre-convert kernels
// ---------------------------------------------------------------------------
__global__ void cvt_x_kernel(const float* __restrict__ x) {
    size_t j = (size_t)blockIdx.x * blockDim.x + threadIdx.x;   // 8 elems each
    if (j >= (size_t)M_ROWS * 32) return;
    const float4* xs = (const float4*)x;
    float4 f0 = xs[j * 2], f1 = xs[j * 2 + 1];
    uint4 u;
    u.x = packh2(f0.x, f0.y); u.y = packh2(f0.z, f0.w);
    u.z = packh2(f1.x, f1.y); u.w = packh2(f1.z, f1.w);
    ((uint4*)g_xh)[j] = u;
}

__global__ void cvt_w_kernel(const float* __restrict__ Wq, const float* __restrict__ Wk,
                             const float* __restrict__ Wv, const float* __restrict__ Wo) {
    int i = blockIdx.x * blockDim.x + threadIdx.x;
    if (i < 65536) {
        int n = i >> 8, k = i & 255;
        g_wqt[i] = __float2half(Wq[k * 256 + n]);
    } else if (i < 98304) {
        int i2 = i - 65536;
        int n = i2 >> 8, k = i2 & 255;
        g_wkt[i2] = __float2half(Wk[k * 128 + n]);
    } else if (i < 131072) {
        int i2 = i - 98304;
        int n = i2 >> 8, k = i2 & 255;
        g_wvt[i2] = __float2half(Wv[k * 128 + n]);
    } else if (i < 196608) {
        int i2 = i - 131072;
        int n = i2 >> 8, k = i2 & 255;
        g_wot[i2] = __float2half(Wo[k * 256 + n]);
    }
}

// ---------------------------------------------------------------------------
// RoPE table
// ---------------------------------------------------------------------------
__global__ void rope_table_kernel() {
    int idx = blockIdx.x * blockDim.x + threadIdx.x;
    if (idx >= TT * 32) return;
    int t = idx >> 5, p = idx & 31;
    const float kLog2_10000_over32 = 0.41524101186407246f;
    float inv = exp2f(-(float)p * kLog2_10000_over32);
    float c, s;
    sincosf((float)t * inv, &s, &c);
    g_rt[idx] = make_float2(c, s);
}

// ---------------------------------------------------------------------------
// fp16 m16n8k16 GEMM tile, 2-stage double buffer (measured best), warp tile
// 32x64 (rope pairs register-local). MODE 0: float out. 1: half. 2: rope half.
// ---------------------------------------------------------------------------
#define HSTR 40
#define HOP_HALVES (128 * HSTR)
#define HSTAGE_HALVES (2 * HOP_HALVES)
#define HSMEM_BYTES (2 * HSTAGE_HALVES * 2)  // 40960

template <int MODE>
__device__ __forceinline__ void hgemm_tile_128(const __half* __restrict__ Ah,
                                               const __half* __restrict__ Bt,
                                               float* __restrict__ Cf,
                                               __half* __restrict__ Ch,
                                               int ldC, int rowbase, float scale) {
    extern __shared__ __half hsm[];
    const uint32_t sbase = smem_u32(hsm);

    const int tid  = threadIdx.x;
    const int warp = tid >> 5;
    const int lane = tid & 31;
    const int gid  = lane >> 2;
    const int tig  = lane & 3;
    const int warpM = (warp >> 1) * 32;
    const int warpN = (warp & 1) * 64;

    float acc[2][8][4];
#pragma unroll
    for (int mt = 0; mt < 2; mt++)
#pragma unroll
        for (int nt = 0; nt < 8; nt++)
#pragma unroll
            for (int r = 0; r < 4; r++) acc[mt][nt][r] = 0.f;

    auto load_stage = [&](int stage, int k0) {
        uint32_t sa = sbase + stage * (HSTAGE_HALVES * 2);
        uint32_t sb = sa + HOP_HALVES * 2;
#pragma unroll
        for (int i = 0; i < 2; i++) {
            int id = tid + i * 256;
            int row = id >> 2, c4 = id & 3;
            cp16(sa + row * 80 + c4 * 16, Ah + (size_t)row * 256 + k0 + c4 * 8);
            cp16(sb + row * 80 + c4 * 16, Bt + (size_t)row * 256 + k0 + c4 * 8);
        }
        asm volatile("cp.async.commit_group;" ::: "memory");
    };

    auto compute_stage = [&](int stage) {
        const __half* sa = hsm + stage * HSTAGE_HALVES;
        const __half* sb = sa + HOP_HALVES;
#pragma unroll
        for (int ks = 0; ks < 2; ks++) {
            const int kc = ks * 16;
            uint32_t bf[8][2];
#pragma unroll
            for (int nt = 0; nt < 8; nt++) {
                int n = warpN + nt * 8 + gid;
                bf[nt][0] = *(const uint32_t*)&sb[n * HSTR + kc + 2 * tig];
                bf[nt][1] = *(const uint32_t*)&sb[n * HSTR + kc + 8 + 2 * tig];
            }
#pragma unroll
            for (int mt = 0; mt < 2; mt++) {
                int r = warpM + mt * 16 + gid;
                uint32_t af[4];
                af[0] = *(const uint32_t*)&sa[r * HSTR + kc + 2 * tig];
                af[1] = *(const uint32_t*)&sa[(r + 8) * HSTR + kc + 2 * tig];
                af[2] = *(const uint32_t*)&sa[r * HSTR + kc + 8 + 2 * tig];
                af[3] = *(const uint32_t*)&sa[(r + 8) * HSTR + kc + 8 + 2 * tig];
#pragma unroll
                for (int nt = 0; nt < 8; nt++) mma_f16(acc[mt][nt], af, bf[nt]);
            }
        }
    };

    load_stage(0, 0);
#pragma unroll
    for (int it = 0; it < 8; it++) {
        if (it + 1 < 8) {
            load_stage((it + 1) & 1, (it + 1) * 32);
            asm volatile("cp.async.wait_group 1;" ::: "memory");
        } else {
            asm volatile("cp.async.wait_group 0;" ::: "memory");
        }
        __syncthreads();
        compute_stage(it & 1);
        __syncthreads();
    }

    // ---- epilogue ----
    if (MODE == 0) {
#pragma unroll
        for (int mt = 0; mt < 2; mt++) {
            int row = rowbase + warpM + mt * 16 + gid;
#pragma unroll
            for (int nt = 0; nt < 8; nt++) {
                int col = warpN + nt * 8 + tig * 2;
                *(float2*)(Cf + (size_t)row * ldC + col) =
                    make_float2(acc[mt][nt][0], acc[mt][nt][1]);
                *(float2*)(Cf + (size_t)(row + 8) * ldC + col) =
                    make_float2(acc[mt][nt][2], acc[mt][nt][3]);
            }
        }
    } else if (MODE == 1) {
#pragma unroll
        for (int mt = 0; mt < 2; mt++) {
            int row = rowbase + warpM + mt * 16 + gid;
#pragma unroll
            for (int nt = 0; nt < 8; nt++) {
                int col = warpN + nt * 8 + tig * 2;
                *(uint32_t*)(Ch + (size_t)row * ldC + col) =
                    packh2(acc[mt][nt][0], acc[mt][nt][1]);
                *(uint32_t*)(Ch + (size_t)(row + 8) * ldC + col) =
                    packh2(acc[mt][nt][2], acc[mt][nt][3]);
            }
        }
    } else {
        // rope: pair (p, p+32) = (nt, nt+4), register-local
#pragma unroll
        for (int mt = 0; mt < 2; mt++) {
            int r0 = warpM + mt * 16 + gid;
#pragma unroll
            for (int nt = 0; nt < 4; nt++) {
                int p = nt * 8 + 2 * tig;
#pragma unroll
                for (int cp = 0; cp < 2; cp++) {
                    int row = rowbase + r0 + cp * 8;
                    int t = row % TT;
                    float2 cs0 = g_rt[t * 32 + p];
                    float2 cs1 = g_rt[t * 32 + p + 1];
                    float v1a = acc[mt][nt][cp * 2 + 0];
                    float v1b = acc[mt][nt][cp * 2 + 1];
                    float v2a = acc[mt][nt + 4][cp * 2 + 0];
                    float v2b = acc[mt][nt + 4][cp * 2 + 1];
                    __half* base = Ch + (size_t)row * ldC + warpN + p;
                    *(uint32_t*)base =
                        packh2((v1a * cs0.x - v2a * cs0.y) * scale,
                               (v1b * cs1.x - v2b * cs1.y) * scale);
                    *(uint32_t*)(base + 32) =
                        packh2((v2a * cs0.x + v1a * cs0.y) * scale,
                               (v2b * cs1.x + v1b * cs1.y) * scale);
                }
            }
        }
    }
}

// QKV: bx 0,1 -> q (rope+scale, half); bx 2 -> k (rope, half); bx 3 -> v (half)
__global__ void __launch_bounds__(256, 2)
hgemm_qkv_kernel() {
    const float qscale = 0.18033688011112042f;  // 0.125 * log2(e)
    const int bx = blockIdx.x, by = blockIdx.y;
    const __half* Ah = g_xh + (size_t)by * 128 * 256;
    if (bx < 2) {
        hgemm_tile_128<2>(Ah, g_wqt + bx * 128 * 256, nullptr,
                          g_qkh + bx * 128, 384, by * 128, qscale);
    } else if (bx == 2) {
        hgemm_tile_128<2>(Ah, g_wkt, nullptr,
                          g_qkh + 256, 384, by * 128, 1.f);
    } else {
        hgemm_tile_128<1>(Ah, g_wvt, nullptr, g_vh, 128, by * 128, 1.f);
    }
}

__global__ void __launch_bounds__(256, 2)
hgemm_out_kernel(float* __restrict__ out) {
    const int bx = blockIdx.x, by = blockIdx.y;
    hgemm_tile_128<0>(g_yh + (size_t)by * 128 * 256, g_wot + bx * 128 * 256,
                      out + bx * 128, nullptr, 256, by * 128, 1.f);
}

// ---------------------------------------------------------------------------
// fp16 flash attention, 2 q-heads per CTA sharing K/V staging (GQA).
// Grid (T/64, KV, B), 256 threads. Warps 0-3: head 2g, warps 4-7: head 2g+1.
// Kh natural [key][d] stride 72, Vt transposed [d][key] stride 72.
// Q A-frags read directly from gmem (no smem staging).
// ---------------------------------------------------------------------------
#define AST 72

__global__ void __launch_bounds__(256)
attn_mma_kernel() {
    __shared__ __half Kh[64 * AST];
    __shared__ __half Vt[64 * AST];

    const int qb = blockIdx.x;      // q tile 0..5
    const int g  = blockIdx.y;      // kv head
    const int b  = blockIdx.z;
    const int tid = threadIdx.x;
    const int w = tid >> 5;
    const int hh = w >> 2;          // head select within kv group
    const int ww = w & 3;           // warp within head
    const int lane = tid & 31;
    const int gid = lane >> 2;
    const int tig = lane & 3;
    const int h = 2 * g + hh;
    const uint32_t sKh = smem_u32(Kh);

    const __half* qh = g_qkh + (size_t)(b * TT) * 384 + h * 64;
    const __half* kh = g_qkh + (size_t)(b * TT) * 384 + 256 + g * 64;
    const __half* vh = g_vh + (size_t)(b * TT) * 128 + g * 64;

    // ---- Q A-fragments straight from gmem (roped+scaled already) ----
    uint32_t aq[4][4];
    {
        const __half* q0 = qh + (size_t)(qb * 64 + ww * 16 + gid) * 384;
        const __half* q1 = q0 + (size_t)8 * 384;
#pragma unroll
        for (int o = 0; o < 4; o++) {
            aq[o][0] = *(const uint32_t*)(q0 + o * 16 + 2 * tig);
            aq[o][1] = *(const uint32_t*)(q1 + o * 16 + 2 * tig);
            aq[o][2] = *(const uint32_t*)(q0 + o * 16 + 8 + 2 * tig);
            aq[o][3] = *(const uint32_t*)(q1 + o * 16 + 8 + 2 * tig);
        }
    }

    float m0 = -1e30f, m1 = -1e30f, l0 = 0.f, l1 = 0.f;
    float oacc[8][4];
#pragma unroll
    for (int nf = 0; nf < 8; nf++)
#pragma unroll
        for (int c = 0; c < 4; c++) oacc[nf][c] = 0.f;

    for (int kt = 0; kt <= qb; kt++) {
        const int kb = kt * 64;
        __syncthreads();   // prior tile's smem reads complete

        // K: cp.async copy, natural [key][d]
#pragma unroll
        for (int it = 0; it < 2; it++) {
            int i = tid + it * 256;
            int key = i >> 3, c8 = i & 7;
            cp16(sKh + (key * AST + c8 * 8) * 2,
                 kh + (size_t)(kb + key) * 384 + c8 * 8);
        }
        asm volatile("cp.async.commit_group;" ::: "memory");
        // V: transpose-store [d][key]
#pragma unroll
        for (int it = 0; it < 2; it++) {
            int i = tid + it * 256;
            int key = i & 63, d8 = i >> 6;
            uint4 v = *(const uint4*)(vh + (size_t)(kb + key) * 128 + d8 * 8);
            const __half* hp = (const __half*)&v;
#pragma unroll
            for (int j = 0; j < 8; j++)
                Vt[(d8 * 8 + j) * AST + key] = hp[j];
        }
        asm volatile("cp.async.wait_group 0;" ::: "memory");
        __syncthreads();

        // ---- S = Q @ K^T ----
        float sacc[8][4];
#pragma unroll
        for (int nf = 0; nf < 8; nf++)
#pragma unroll
            for (int c = 0; c < 4; c++) sacc[nf][c] = 0.f;
#pragma unroll
        for (int nf = 0; nf < 8; nf++) {
#pragma unroll
            for (int o = 0; o < 4; o++) {
                uint32_t bk[2];
                bk[0] = *(const uint32_t*)&Kh[(nf * 8 + gid) * AST + o * 16 + 2 * tig];
                bk[1] = *(const uint32_t*)&Kh[(nf * 8 + gid) * AST + o * 16 + 8 + 2 * tig];
                mma_f16(sacc[nf], aq[o], bk);
            }
        }

        // ---- causal mask on diagonal tile ----
        if (kt == qb) {
            int jr0 = ww * 16 + gid, jr1 = jr0 + 8;
#pragma unroll
            for (int nf = 0; nf < 8; nf++) {
                int jc = nf * 8 + 2 * tig;
                if (jc > jr0)     sacc[nf][0] = -1e30f;
                if (jc + 1 > jr0) sacc[nf][1] = -1e30f;
                if (jc > jr1)     sacc[nf][2] = -1e30f;
                if (jc + 1 > jr1) sacc[nf][3] = -1e30f;
            }
        }

        // ---- online softmax (exp2 domain) ----
        float rx0 = -1e30f, rx1 = -1e30f;
#pragma unroll
        for (int nf = 0; nf < 8; nf++) {
            rx0 = fmaxf(rx0, fmaxf(sacc[nf][0], sacc[nf][1]));
            rx1 = fmaxf(rx1, fmaxf(sacc[nf][2], sacc[nf][3]));
        }
        rx0 = fmaxf(rx0, __shfl_xor_sync(0xffffffffu, rx0, 1));
        rx0 = fmaxf(rx0, __shfl_xor_sync(0xffffffffu, rx0, 2));
        rx1 = fmaxf(rx1, __shfl_xor_sync(0xffffffffu, rx1, 1));
        rx1 = fmaxf(rx1, __shfl_xor_sync(0xffffffffu, rx1, 2));
        float mn0 = fmaxf(m0, rx0), mn1 = fmaxf(m1, rx1);
        float corr0 = exp2f(m0 - mn0), corr1 = exp2f(m1 - mn1);
        m0 = mn0; m1 = mn1;
        float rs0 = 0.f, rs1 = 0.f;
#pragma unroll
        for (int nf = 0; nf < 8; nf++) {
            sacc[nf][0] = exp2f(sacc[nf][0] - m0);
            sacc[nf][1] = exp2f(sacc[nf][1] - m0);
            sacc[nf][2] = exp2f(sacc[nf][2] - m1);
            sacc[nf][3] = exp2f(sacc[nf][3] - m1);
            rs0 += sacc[nf][0] + sacc[nf][1];
            rs1 += sacc[nf][2] + sacc[nf][3];
        }
        rs0 += __shfl_xor_sync(0xffffffffu, rs0, 1);
        rs0 += __shfl_xor_sync(0xffffffffu, rs0, 2);
        rs1 += __shfl_xor_sync(0xffffffffu, rs1, 1);
        rs1 += __shfl_xor_sync(0xffffffffu, rs1, 2);
        l0 = l0 * corr0 + rs0;
        l1 = l1 * corr1 + rs1;
#pragma unroll
        for (int nf = 0; nf < 8; nf++) {
            oacc[nf][0] *= corr0; oacc[nf][1] *= corr0;
            oacc[nf][2] *= corr1; oacc[nf][3] *= corr1;
        }

        // ---- O += P @ V : S C-layout IS the f16 A-layout (no shuffles) ----
#pragma unroll
        for (int ko = 0; ko < 4; ko++) {
            uint32_t pa[4];
            pa[0] = packh2(sacc[2 * ko][0], sacc[2 * ko][1]);
            pa[1] = packh2(sacc[2 * ko][2], sacc[2 * ko][3]);
            pa[2] = packh2(sacc[2 * ko + 1][0], sacc[2 * ko + 1][1]);
            pa[3] = packh2(sacc[2 * ko + 1][2], sacc[2 * ko + 1][3]);
#pragma unroll
            for (int nd = 0; nd < 8; nd++) {
                uint32_t bv[2];
                bv[0] = *(const uint32_t*)&Vt[(nd * 8 + gid) * AST + ko * 16 + 2 * tig];
                bv[1] = *(const uint32_t*)&Vt[(nd * 8 + gid) * AST + ko * 16 + 8 + 2 * tig];
                mma_f16(oacc[nd], pa, bv);
            }
        }
    }

    // ---- epilogue: write half ----
    float il0 = 1.f / l0, il1 = 1.f / l1;
    __half* y0 = g_yh + (size_t)(b * TT + qb * 64 + ww * 16 + gid) * 256 + h * 64;
    __half* y1 = y0 + (size_t)8 * 256;
#pragma unroll
    for (int nf = 0; nf < 8; nf++) {
        *(uint32_t*)(y0 + nf * 8 + 2 * tig) =
            packh2(oacc[nf][0] * il0, oacc[nf][1] * il0);
        *(uint32_t*)(y1 + nf * 8 + 2 * tig) =
            packh2(oacc[nf][2] * il1, oacc[nf][3] * il1);
    }
}

// ---------------------------------------------------------------------------
extern "C" void kernel_launch(void* const* d_in, const int* in_sizes, int n_in,
                              void* d_out, int out_size) {
    const float* x  = (const float*)d_in[0];
    const float* Wq = (const float*)d_in[1];
    const float* Wk = (const float*)d_in[2];
    const float* Wv = (const float*)d_in[3];
    const float* Wo = (const float*)d_in[4];
    float* out = (float*)d_out;

    cudaFuncSetAttribute(hgemm_qkv_kernel,
                         cudaFuncAttributeMaxDynamicSharedMemorySize, HSMEM_BYTES);
    cudaFuncSetAttribute(hgemm_out_kernel,
                         cudaFuncAttributeMaxDynamicSharedMemorySize, HSMEM_BYTES);

    rope_table_kernel<<<(TT * 32 + 255) / 256, 256>>>();
    cvt_x_kernel<<<(M_ROWS * 32 + 255) / 256, 256>>>(x);
    cvt_w_kernel<<<(196608 + 255) / 256, 256>>>(Wq, Wk, Wv, Wo);

    // QKV projection with fused rope epilogue -> g_qkh (half), g_vh (half)
    hgemm_qkv_kernel<<<dim3(4, M_ROWS / 128), 256, HSMEM_BYTES>>>();

    // fp16 flash attention (2 heads/CTA share K/V) -> g_yh
    {
        dim3 ga(TT / 64, NKV, BB);
        attn_mma_kernel<<<ga, 256>>>();
    }

    // output projection
    hgemm_out_kernel<<<dim3(2, M_ROWS / 128), 256, HSMEM_BYTES>>>(out);
}

// round 17
// speedup vs baseline: 2.1071x; 1.0081x over previous
#include <cuda_runtime.h>
#include <cuda_fp16.h>
#include <cstdint>
#include <math.h>

#define BB 128
#define TT 384
#define CC 256
#define NH 4
#define NKV 2
#define HD 64
#define M_ROWS (BB * TT)   // 49152

// ---------------- scratch (device globals; allocation is forbidden) --------
__device__ __align__(16) __half g_xh[(size_t)M_ROWS * 256];   // x in half
__device__ __align__(16) __half g_qkh[(size_t)M_ROWS * 384];  // roped q|k half
__device__ __align__(16) __half g_vh[(size_t)M_ROWS * 128];   // v half
__device__ __align__(16) __half g_yh[(size_t)M_ROWS * CC];    // attn out half
__device__ __align__(16) __half g_wqt[256 * 256];             // W^T half [n][k]
__device__ __align__(16) __half g_wkt[128 * 256];
__device__ __align__(16) __half g_wvt[128 * 256];
__device__ __align__(16) __half g_wot[256 * 256];
__device__ float2 g_rt[TT * 32];                              // rope table

// ---------------- helpers ---------------------------------------------------
__device__ __forceinline__ uint32_t smem_u32(const void* p) {
    uint32_t a;
    asm("{ .reg .u64 t; cvta.to.shared.u64 t, %1; cvt.u32.u64 %0, t; }"
        : "=r"(a) : "l"(p));
    return a;
}
__device__ __forceinline__ void cp16(uint32_t s, const void* g) {
    asm volatile("cp.async.cg.shared.global [%0], [%1], 16;" :: "r"(s), "l"(g));
}
__device__ __forceinline__ void mma_f16(float* d, const uint32_t* a, const uint32_t* b) {
    asm volatile(
        "mma.sync.aligned.m16n8k16.row.col.f32.f16.f16.f32 "
        "{%0,%1,%2,%3}, {%4,%5,%6,%7}, {%8,%9}, {%0,%1,%2,%3};"
        : "+f"(d[0]), "+f"(d[1]), "+f"(d[2]), "+f"(d[3])
        : "r"(a[0]), "r"(a[1]), "r"(a[2]), "r"(a[3]), "r"(b[0]), "r"(b[1]));
}
__device__ __forceinline__ void ldsm_x4(uint32_t& r0, uint32_t& r1,
                                        uint32_t& r2, uint32_t& r3, uint32_t addr) {
    asm volatile("ldmatrix.sync.aligned.m8n8.x4.shared.b16 {%0,%1,%2,%3}, [%4];"
                 : "=r"(r0), "=r"(r1), "=r"(r2), "=r"(r3) : "r"(addr));
}
__device__ __forceinline__ uint32_t packh2(float a, float b) {
    __half2 h = __floats2half2_rn(a, b);
    return *(uint32_t*)&h;
}

// ---------------------------------------------------------------------------
// Pre-convert kernels
// ---------------------------------------------------------------------------
__global__ void cvt_x_kernel(const float* __restrict__ x) {
    size_t j = (size_t)blockIdx.x * blockDim.x + threadIdx.x;   // 8 elems each
    if (j >= (size_t)M_ROWS * 32) return;
    const float4* xs = (const float4*)x;
    float4 f0 = xs[j * 2], f1 = xs[j * 2 + 1];
    uint4 u;
    u.x = packh2(f0.x, f0.y); u.y = packh2(f0.z, f0.w);
    u.z = packh2(f1.x, f1.y); u.w = packh2(f1.z, f1.w);
    ((uint4*)g_xh)[j] = u;
}

__global__ void cvt_w_kernel(const float* __restrict__ Wq, const float* __restrict__ Wk,
                             const float* __restrict__ Wv, const float* __restrict__ Wo) {
    int i = blockIdx.x * blockDim.x + threadIdx.x;
    if (i < 65536) {
        int n = i >> 8, k = i & 255;
        g_wqt[i] = __float2half(Wq[k * 256 + n]);
    } else if (i < 98304) {
        int i2 = i - 65536;
        int n = i2 >> 8, k = i2 & 255;
        g_wkt[i2] = __float2half(Wk[k * 128 + n]);
    } else if (i < 131072) {
        int i2 = i - 98304;
        int n = i2 >> 8, k = i2 & 255;
        g_wvt[i2] = __float2half(Wv[k * 128 + n]);
    } else if (i < 196608) {
        int i2 = i - 131072;
        int n = i2 >> 8, k = i2 & 255;
        g_wot[i2] = __float2half(Wo[k * 256 + n]);
    }
}

// ---------------------------------------------------------------------------
// RoPE table
// ---------------------------------------------------------------------------
__global__ void rope_table_kernel() {
    int idx = blockIdx.x * blockDim.x + threadIdx.x;
    if (idx >= TT * 32) return;
    int t = idx >> 5, p = idx & 31;
    const float kLog2_10000_over32 = 0.41524101186407246f;
    float inv = exp2f(-(float)p * kLog2_10000_over32);
    float c, s;
    sincosf((float)t * inv, &s, &c);
    g_rt[idx] = make_float2(c, s);
}

// ---------------------------------------------------------------------------
// fp16 m16n8k16 GEMM tile, 2-stage double buffer, warp tile 32x64, fragment
// loads via ldmatrix.x4 (12 per iter vs 48 LDS.32). Stride-40-half padding is
// ldmatrix-conflict-free: rows hit banks 20i mod 32, spans cover all 32 banks.
// MODE 0: float out. 1: half. 2: rope half.
// ---------------------------------------------------------------------------
#define HSTR 40
#define HOP_HALVES (128 * HSTR)
#define HSTAGE_HALVES (2 * HOP_HALVES)
#define HSMEM_BYTES (2 * HSTAGE_HALVES * 2)  // 40960

template <int MODE>
__device__ __forceinline__ void hgemm_tile_128(const __half* __restrict__ Ah,
                                               const __half* __restrict__ Bt,
                                               float* __restrict__ Cf,
                                               __half* __restrict__ Ch,
                                               int ldC, int rowbase, float scale) {
    extern __shared__ __half hsm[];
    const uint32_t sbase = smem_u32(hsm);

    const int tid  = threadIdx.x;
    const int warp = tid >> 5;
    const int lane = tid & 31;
    const int gid  = lane >> 2;
    const int tig  = lane & 3;
    const int warpM = (warp >> 1) * 32;
    const int warpN = (warp & 1) * 64;
    // ldmatrix lane-address components: lane group m supplies matrix m's rows
    const int lm = lane >> 3;       // 0..3: matrix index within x4
    const int lr = lane & 7;        // row within matrix
    const int mrow = (lm & 1) * 8 + lr;      // row offset 0..15
    const int mkof = (lm >> 1) * 8;          // k offset 0 or 8

    float acc[2][8][4];
#pragma unroll
    for (int mt = 0; mt < 2; mt++)
#pragma unroll
        for (int nt = 0; nt < 8; nt++)
#pragma unroll
            for (int r = 0; r < 4; r++) acc[mt][nt][r] = 0.f;

    auto load_stage = [&](int stage, int k0) {
        uint32_t sa = sbase + stage * (HSTAGE_HALVES * 2);
        uint32_t sb = sa + HOP_HALVES * 2;
#pragma unroll
        for (int i = 0; i < 2; i++) {
            int id = tid + i * 256;
            int row = id >> 2, c4 = id & 3;
            cp16(sa + row * 80 + c4 * 16, Ah + (size_t)row * 256 + k0 + c4 * 8);
            cp16(sb + row * 80 + c4 * 16, Bt + (size_t)row * 256 + k0 + c4 * 8);
        }
        asm volatile("cp.async.commit_group;" ::: "memory");
    };

    auto compute_stage = [&](int stage) {
        const uint32_t sa = sbase + stage * (HSTAGE_HALVES * 2);
        const uint32_t sb = sa + HOP_HALVES * 2;
#pragma unroll
        for (int ks = 0; ks < 2; ks++) {
            const int kc = ks * 16;
            uint32_t bf[8][2];
#pragma unroll
            for (int ng = 0; ng < 4; ng++) {
                uint32_t addr = sb +
                    ((warpN + ng * 16 + mrow) * HSTR + kc + mkof) * 2;
                ldsm_x4(bf[2 * ng][0], bf[2 * ng + 1][0],
                        bf[2 * ng][1], bf[2 * ng + 1][1], addr);
            }
#pragma unroll
            for (int mt = 0; mt < 2; mt++) {
                uint32_t af[4];
                uint32_t addr = sa +
                    ((warpM + mt * 16 + mrow) * HSTR + kc + mkof) * 2;
                ldsm_x4(af[0], af[1], af[2], af[3], addr);
#pragma unroll
                for (int nt = 0; nt < 8; nt++) mma_f16(acc[mt][nt], af, bf[nt]);
            }
        }
    };

    load_stage(0, 0);
#pragma unroll
    for (int it = 0; it < 8; it++) {
        if (it + 1 < 8) {
            load_stage((it + 1) & 1, (it + 1) * 32);
            asm volatile("cp.async.wait_group 1;" ::: "memory");
        } else {
            asm volatile("cp.async.wait_group 0;" ::: "memory");
        }
        __syncthreads();
        compute_stage(it & 1);
        __syncthreads();
    }

    // ---- epilogue ----
    if (MODE == 0) {
#pragma unroll
        for (int mt = 0; mt < 2; mt++) {
            int row = rowbase + warpM + mt * 16 + gid;
#pragma unroll
            for (int nt = 0; nt < 8; nt++) {
                int col = warpN + nt * 8 + tig * 2;
                *(float2*)(Cf + (size_t)row * ldC + col) =
                    make_float2(acc[mt][nt][0], acc[mt][nt][1]);
                *(float2*)(Cf + (size_t)(row + 8) * ldC + col) =
                    make_float2(acc[mt][nt][2], acc[mt][nt][3]);
            }
        }
    } else if (MODE == 1) {
#pragma unroll
        for (int mt = 0; mt < 2; mt++) {
            int row = rowbase + warpM + mt * 16 + gid;
#pragma unroll
            for (int nt = 0; nt < 8; nt++) {
                int col = warpN + nt * 8 + tig * 2;
                *(uint32_t*)(Ch + (size_t)row * ldC + col) =
                    packh2(acc[mt][nt][0], acc[mt][nt][1]);
                *(uint32_t*)(Ch + (size_t)(row + 8) * ldC + col) =
                    packh2(acc[mt][nt][2], acc[mt][nt][3]);
            }
        }
    } else {
        // rope: pair (p, p+32) = (nt, nt+4), register-local
#pragma unroll
        for (int mt = 0; mt < 2; mt++) {
            int r0 = warpM + mt * 16 + gid;
#pragma unroll
            for (int nt = 0; nt < 4; nt++) {
                int p = nt * 8 + 2 * tig;
#pragma unroll
                for (int cp = 0; cp < 2; cp++) {
                    int row = rowbase + r0 + cp * 8;
                    int t = row % TT;
                    float2 cs0 = g_rt[t * 32 + p];
                    float2 cs1 = g_rt[t * 32 + p + 1];
                    float v1a = acc[mt][nt][cp * 2 + 0];
                    float v1b = acc[mt][nt][cp * 2 + 1];
                    float v2a = acc[mt][nt + 4][cp * 2 + 0];
                    float v2b = acc[mt][nt + 4][cp * 2 + 1];
                    __half* base = Ch + (size_t)row * ldC + warpN + p;
                    *(uint32_t*)base =
                        packh2((v1a * cs0.x - v2a * cs0.y) * scale,
                               (v1b * cs1.x - v2b * cs1.y) * scale);
                    *(uint32_t*)(base + 32) =
                        packh2((v2a * cs0.x + v1a * cs0.y) * scale,
                               (v2b * cs1.x + v1b * cs1.y) * scale);
                }
            }
        }
    }
}

// QKV: bx 0,1 -> q (rope+scale, half); bx 2 -> k (rope, half); bx 3 -> v (half)
__global__ void __launch_bounds__(256, 2)
hgemm_qkv_kernel() {
    const float qscale = 0.18033688011112042f;  // 0.125 * log2(e)
    const int bx = blockIdx.x, by = blockIdx.y;
    const __half* Ah = g_xh + (size_t)by * 128 * 256;
    if (bx < 2) {
        hgemm_tile_128<2>(Ah, g_wqt + bx * 128 * 256, nullptr,
                          g_qkh + bx * 128, 384, by * 128, qscale);
    } else if (bx == 2) {
        hgemm_tile_128<2>(Ah, g_wkt, nullptr,
                          g_qkh + 256, 384, by * 128, 1.f);
    } else {
        hgemm_tile_128<1>(Ah, g_wvt, nullptr, g_vh, 128, by * 128, 1.f);
    }
}

__global__ void __launch_bounds__(256, 2)
hgemm_out_kernel(float* __restrict__ out) {
    const int bx = blockIdx.x, by = blockIdx.y;
    hgemm_tile_128<0>(g_yh + (size_t)by * 128 * 256, g_wot + bx * 128 * 256,
                      out + bx * 128, nullptr, 256, by * 128, 1.f);
}

// ---------------------------------------------------------------------------
// fp16 flash attention, 2 q-heads per CTA sharing K/V staging (GQA).
// Grid (T/64, KV, B), 256 threads. (Unchanged from R16, measured-good.)
// ---------------------------------------------------------------------------
#define AST 72

__global__ void __launch_bounds__(256)
attn_mma_kernel() {
    __shared__ __half Kh[64 * AST];
    __shared__ __half Vt[64 * AST];

    const int qb = blockIdx.x;      // q tile 0..5
    const int g  = blockIdx.y;      // kv head
    const int b  = blockIdx.z;
    const int tid = threadIdx.x;
    const int w = tid >> 5;
    const int hh = w >> 2;          // head select within kv group
    const int ww = w & 3;           // warp within head
    const int lane = tid & 31;
    const int gid = lane >> 2;
    const int tig = lane & 3;
    const int h = 2 * g + hh;
    const uint32_t sKh = smem_u32(Kh);

    const __half* qh = g_qkh + (size_t)(b * TT) * 384 + h * 64;
    const __half* kh = g_qkh + (size_t)(b * TT) * 384 + 256 + g * 64;
    const __half* vh = g_vh + (size_t)(b * TT) * 128 + g * 64;

    // ---- Q A-fragments straight from gmem (roped+scaled already) ----
    uint32_t aq[4][4];
    {
        const __half* q0 = qh + (size_t)(qb * 64 + ww * 16 + gid) * 384;
        const __half* q1 = q0 + (size_t)8 * 384;
#pragma unroll
        for (int o = 0; o < 4; o++) {
            aq[o][0] = *(const uint32_t*)(q0 + o * 16 + 2 * tig);
            aq[o][1] = *(const uint32_t*)(q1 + o * 16 + 2 * tig);
            aq[o][2] = *(const uint32_t*)(q0 + o * 16 + 8 + 2 * tig);
            aq[o][3] = *(const uint32_t*)(q1 + o * 16 + 8 + 2 * tig);
        }
    }

    float m0 = -1e30f, m1 = -1e30f, l0 = 0.f, l1 = 0.f;
    float oacc[8][4];
#pragma unroll
    for (int nf = 0; nf < 8; nf++)
#pragma unroll
        for (int c = 0; c < 4; c++) oacc[nf][c] = 0.f;

    for (int kt = 0; kt <= qb; kt++) {
        const int kb = kt * 64;
        __syncthreads();   // prior tile's smem reads complete

        // K: cp.async copy, natural [key][d]
#pragma unroll
        for (int it = 0; it < 2; it++) {
            int i = tid + it * 256;
            int key = i >> 3, c8 = i & 7;
            cp16(sKh + (key * AST + c8 * 8) * 2,
                 kh + (size_t)(kb + key) * 384 + c8 * 8);
        }
        asm volatile("cp.async.commit_group;" ::: "memory");
        // V: transpose-store [d][key]
#pragma unroll
        for (int it = 0; it < 2; it++) {
            int i = tid + it * 256;
            int key = i & 63, d8 = i >> 6;
            uint4 v = *(const uint4*)(vh + (size_t)(kb + key) * 128 + d8 * 8);
            const __half* hp = (const __half*)&v;
#pragma unroll
            for (int j = 0; j < 8; j++)
                Vt[(d8 * 8 + j) * AST + key] = hp[j];
        }
        asm volatile("cp.async.wait_group 0;" ::: "memory");
        __syncthreads();

        // ---- S = Q @ K^T ----
        float sacc[8][4];
#pragma unroll
        for (int nf = 0; nf < 8; nf++)
#pragma unroll
            for (int c = 0; c < 4; c++) sacc[nf][c] = 0.f;
#pragma unroll
        for (int nf = 0; nf < 8; nf++) {
#pragma unroll
            for (int o = 0; o < 4; o++) {
                uint32_t bk[2];
                bk[0] = *(const uint32_t*)&Kh[(nf * 8 + gid) * AST + o * 16 + 2 * tig];
                bk[1] = *(const uint32_t*)&Kh[(nf * 8 + gid) * AST + o * 16 + 8 + 2 * tig];
                mma_f16(sacc[nf], aq[o], bk);
            }
        }

        // ---- causal mask on diagonal tile ----
        if (kt == qb) {
            int jr0 = ww * 16 + gid, jr1 = jr0 + 8;
#pragma unroll
            for (int nf = 0; nf < 8; nf++) {
                int jc = nf * 8 + 2 * tig;
                if (jc > jr0)     sacc[nf][0] = -1e30f;
                if (jc + 1 > jr0) sacc[nf][1] = -1e30f;
                if (jc > jr1)     sacc[nf][2] = -1e30f;
                if (jc + 1 > jr1) sacc[nf][3] = -1e30f;
            }
        }

        // ---- online softmax (exp2 domain) ----
        float rx0 = -1e30f, rx1 = -1e30f;
#pragma unroll
        for (int nf = 0; nf < 8; nf++) {
            rx0 = fmaxf(rx0, fmaxf(sacc[nf][0], sacc[nf][1]));
            rx1 = fmaxf(rx1, fmaxf(sacc[nf][2], sacc[nf][3]));
        }
        rx0 = fmaxf(rx0, __shfl_xor_sync(0xffffffffu, rx0, 1));
        rx0 = fmaxf(rx0, __shfl_xor_sync(0xffffffffu, rx0, 2));
        rx1 = fmaxf(rx1, __shfl_xor_sync(0xffffffffu, rx1, 1));
        rx1 = fmaxf(rx1, __shfl_xor_sync(0xffffffffu, rx1, 2));
        float mn0 = fmaxf(m0, rx0), mn1 = fmaxf(m1, rx1);
        float corr0 = exp2f(m0 - mn0), corr1 = exp2f(m1 - mn1);
        m0 = mn0; m1 = mn1;
        float rs0 = 0.f, rs1 = 0.f;
#pragma unroll
        for (int nf = 0; nf < 8; nf++) {
            sacc[nf][0] = exp2f(sacc[nf][0] - m0);
            sacc[nf][1] = exp2f(sacc[nf][1] - m0);
            sacc[nf][2] = exp2f(sacc[nf][2] - m1);
            sacc[nf][3] = exp2f(sacc[nf][3] - m1);
            rs0 += sacc[nf][0] + sacc[nf][1];
            rs1 += sacc[nf][2] + sacc[nf][3];
        }
        rs0 += __shfl_xor_sync(0xffffffffu, rs0, 1);
        rs0 += __shfl_xor_sync(0xffffffffu, rs0, 2);
        rs1 += __shfl_xor_sync(0xffffffffu, rs1, 1);
        rs1 += __shfl_xor_sync(0xffffffffu, rs1, 2);
        l0 = l0 * corr0 + rs0;
        l1 = l1 * corr1 + rs1;
#pragma unroll
        for (int nf = 0; nf < 8; nf++) {
            oacc[nf][0] *= corr0; oacc[nf][1] *= corr0;
            oacc[nf][2] *= corr1; oacc[nf][3] *= corr1;
        }

        // ---- O += P @ V : S C-layout IS the f16 A-layout (no shuffles) ----
#pragma unroll
        for (int ko = 0; ko < 4; ko++) {
            uint32_t pa[4];
            pa[0] = packh2(sacc[2 * ko][0], sacc[2 * ko][1]);
            pa[1] = packh2(sacc[2 * ko][2], sacc[2 * ko][3]);
            pa[2] = packh2(sacc[2 * ko + 1][0], sacc[2 * ko + 1][1]);
            pa[3] = packh2(sacc[2 * ko + 1][2], sacc[2 * ko + 1][3]);
#pragma unroll
            for (int nd = 0; nd < 8; nd++) {
                uint32_t bv[2];
                bv[0] = *(const uint32_t*)&Vt[(nd * 8 + gid) * AST + ko * 16 + 2 * tig];
                bv[1] = *(const uint32_t*)&Vt[(nd * 8 + gid) * AST + ko * 16 + 8 + 2 * tig];
                mma_f16(oacc[nd], pa, bv);
            }
        }
    }

    // ---- epilogue: write half ----
    float il0 = 1.f / l0, il1 = 1.f / l1;
    __half* y0 = g_yh + (size_t)(b * TT + qb * 64 + ww * 16 + gid) * 256 + h * 64;
    __half* y1 = y0 + (size_t)8 * 256;
#pragma unroll
    for (int nf = 0; nf < 8; nf++) {
        *(uint32_t*)(y0 + nf * 8 + 2 * tig) =
            packh2(oacc[nf][0] * il0, oacc[nf][1] * il0);
        *(uint32_t*)(y1 + nf * 8 + 2 * tig) =
            packh2(oacc[nf][2] * il1, oacc[nf][3] * il1);
    }
}

// ---------------------------------------------------------------------------
extern "C" void kernel_launch(void* const* d_in, const int* in_sizes, int n_in,
                              void* d_out, int out_size) {
    const float* x  = (const float*)d_in[0];
    const float* Wq = (const float*)d_in[1];
    const float* Wk = (const float*)d_in[2];
    const float* Wv = (const float*)d_in[3];
    const float* Wo = (const float*)d_in[4];
    float* out = (float*)d_out;

    cudaFuncSetAttribute(hgemm_qkv_kernel,
                         cudaFuncAttributeMaxDynamicSharedMemorySize, HSMEM_BYTES);
    cudaFuncSetAttribute(hgemm_out_kernel,
                         cudaFuncAttributeMaxDynamicSharedMemorySize, HSMEM_BYTES);

    rope_table_kernel<<<(TT * 32 + 255) / 256, 256>>>();
    cvt_x_kernel<<<(M_ROWS * 32 + 255) / 256, 256>>>(x);
    cvt_w_kernel<<<(196608 + 255) / 256, 256>>>(Wq, Wk, Wv, Wo);

    // QKV projection with fused rope epilogue -> g_qkh (half), g_vh (half)
    hgemm_qkv_kernel<<<dim3(4, M_ROWS / 128), 256, HSMEM_BYTES>>>();

    // fp16 flash attention (2 heads/CTA share K/V) -> g_yh
    {
        dim3 ga(TT / 64, NKV, BB);
        attn_mma_kernel<<<ga, 256>>>();
    }

    // output projection
    hgemm_out_kernel<<<dim3(2, M_ROWS / 128), 256, HSMEM_BYTES>>>(out);
}